// round 14
// baseline (speedup 1.0000x reference)
#include <cuda_runtime.h>
#include <cstdint>
#include <cstring>
#include <cmath>

#define BB 64
#define HH 256
#define WW 256
#define IMGS 224
#define NPIX (IMGS*IMGS)   /* 50176 */
#define NBLK 49            /* 50176 / (256*4) */
#define TILEBLKS 4096      /* 64 images * 64 tiles (8x8 tiles of 32x32) */

#define RROWS 51           /* staged source rows */
#define RCOLS 56           /* staged source cols (x_lo aligned to 4) */
#define RPITCH 60          /* smem pitch in floats (16B-aligned rows) */
#define NV4 14             /* float4 per staged row */

// ---------------- device scratch (static globals; no allocs) ----------------
__device__ float g_xw[BB*3*HH*WW];     // warped 256x256 (planar)
__device__ float g_xc[BB*3*NPIX];      // cropped 224x224 (planar)
__device__ float g_partial[BB*NBLK];   // gray partial sums
__device__ int   g_crop[BB*3];         // x0,y0,s per batch

// ---------------- parameter structs (passed by value) ----------------
struct WarpP { float inv[BB][6]; };
struct CropP { float fb[BB]; };
struct JitP  { float fb[BB], fc[BB], fs[BB], fhue[BB]; int ap[BB]; };
struct BlurP { float ky[BB][3]; float kx[BB][9]; int ap[BB]; };

// ============================================================================
// K1: fused affine-warp (smem-tiled, blocks >= BB) + interval max-square (0..63)
// ============================================================================
__device__ __forceinline__ int coverage_ok(const float* m, float fx, float fy) {
    float sx = m[0]*fx + m[1]*fy + m[2];
    float sy = m[3]*fx + m[4]*fy + m[5];
    float x0f = floorf(sx), y0f = floorf(sy);
    int xi = (int)x0f, yi = (int)y0f;
    float wx = sx - x0f, wy = sy - y0f;
    float i00 = (yi   >= 0 && yi   < HH && xi   >= 0 && xi   < WW) ? 1.f : 0.f;
    float i01 = (yi   >= 0 && yi   < HH && xi+1 >= 0 && xi+1 < WW) ? 1.f : 0.f;
    float i10 = (yi+1 >= 0 && yi+1 < HH && xi   >= 0 && xi   < WW) ? 1.f : 0.f;
    float i11 = (yi+1 >= 0 && yi+1 < HH && xi+1 >= 0 && xi+1 < WW) ? 1.f : 0.f;
    float cov = i00*(1.f-wy)*(1.f-wx) + i01*(1.f-wy)*wx + i10*wy*(1.f-wx) + i11*wy*wx;
    return cov > 0.5f ? 1 : 0;
}

__global__ void __launch_bounds__(256) warp_maxsq_kernel(const float* __restrict__ x, WarpP P) {
    __shared__ __align__(16) char sraw[3*RROWS*RPITCH*4];   // 36.7KB, shared by both roles

    if (blockIdx.x < BB) {
        // -------- maxsq role: mask rows are intervals (convex region) --------
        int* s_L = (int*)sraw;
        int* s_R = s_L + 256;
        int* s_s = s_L + 512;
        int* s_i = s_L + 768;
        int b = blockIdx.x;
        int t = threadIdx.x;            // this thread owns mask row t
        const float* m = P.inv[b];
        float fy = (float)t;
        int L = 256, R = -1;
        #pragma unroll 4
        for (int j = 0; j < WW; j++) {
            if (coverage_ok(m, (float)j, fy)) { if (j < L) L = j; R = j; }
        }
        s_L[t] = L; s_R[t] = R;
        __syncthreads();

        int bs = 0;
        if (R >= L) {
            int Lmax = L, Rmin = R;
            int s = 1;
            while (t - s >= 0) {
                Lmax = max(Lmax, s_L[t - s]);
                Rmin = min(Rmin, s_R[t - s]);
                if (Rmin - Lmax + 1 >= s + 1) s++;
                else break;
            }
            bs = s;
        }
        s_s[t] = bs; s_i[t] = t;
        __syncthreads();
        for (int stride = 128; stride > 0; stride >>= 1) {
            if (t < stride) {
                int v2 = s_s[t+stride], i2 = s_i[t+stride];
                if (v2 > s_s[t] || (v2 == s_s[t] && i2 < s_i[t])) { s_s[t] = v2; s_i[t] = i2; }
            }
            __syncthreads();
        }
        if (t == 0) {
            int s = s_s[0], ii = s_i[0];
            int x0, y0;
            if (s == 0) { x0 = WW/2; y0 = HH/2; s = 1; }
            else {
                int Lmax = -1;
                for (int r = ii - s + 1; r <= ii; r++) Lmax = max(Lmax, s_L[r]);
                int jj = Lmax + s - 1;
                x0 = jj + 1 - s; y0 = ii + 1 - s;
            }
            g_crop[b*3+0] = x0; g_crop[b*3+1] = y0; g_crop[b*3+2] = s;
        }
        return;
    }

    // -------- warp role: 32x32 output tile per block, source staged in smem --
    float (*st)[RROWS][RPITCH] = (float(*)[RROWS][RPITCH])sraw;
    int tb = blockIdx.x - BB;
    int b = tb >> 6;
    int tile = tb & 63;
    int w0t = (tile & 7) << 5;
    int h0t = (tile >> 3) << 5;
    const float* m = P.inv[b];
    int tid = threadIdx.x;

    // bbox of clamped source coords over the tile's 4 corners (affine => hull)
    float f_w0 = (float)w0t, f_w1 = (float)(w0t + 31);
    float f_h0 = (float)h0t, f_h1 = (float)(h0t + 31);
    float sx00 = m[0]*f_w0 + m[1]*f_h0 + m[2];
    float sx10 = m[0]*f_w1 + m[1]*f_h0 + m[2];
    float sx01 = m[0]*f_w0 + m[1]*f_h1 + m[2];
    float sx11 = m[0]*f_w1 + m[1]*f_h1 + m[2];
    float sy00 = m[3]*f_w0 + m[4]*f_h0 + m[5];
    float sy10 = m[3]*f_w1 + m[4]*f_h0 + m[5];
    float sy01 = m[3]*f_w0 + m[4]*f_h1 + m[5];
    float sy11 = m[3]*f_w1 + m[4]*f_h1 + m[5];
    float cminx = fminf(fminf(sx00, sx10), fminf(sx01, sx11));
    float cminy = fminf(fminf(sy00, sy10), fminf(sy01, sy11));
    cminx = fminf(fmaxf(cminx, 0.f), 255.f);
    cminy = fminf(fmaxf(cminy, 0.f), 255.f);
    int x_lo = (max((int)floorf(cminx) - 1, 0)) & ~3;     // 4-aligned
    int y_lo = max((int)floorf(cminy) - 1, 0);

    const float* xb = x + (size_t)b*3*HH*WW;
    if (x_lo + (RCOLS - 1) <= 255) {
        // interior fast path: float4 staging (no column clamp needed)
        #pragma unroll
        for (int c = 0; c < 3; c++) {
            const float4* src = (const float4*)(xb + c*HH*WW + x_lo);
            float4* dst = (float4*)&st[c][0][0];
            for (int k = tid; k < RROWS*NV4; k += 256) {
                int ry = k / NV4;
                int rx4 = k - ry*NV4;
                int gy = min(y_lo + ry, 255);
                dst[ry*(RPITCH/4) + rx4] = __ldg(src + gy*(WW/4) + rx4);
            }
        }
    } else {
        // edge path: scalar staging with per-element clamp (duplicates edge col)
        #pragma unroll
        for (int c = 0; c < 3; c++) {
            const float* src = xb + c*HH*WW;
            for (int k = tid; k < RROWS*RCOLS; k += 256) {
                int ry = k / RCOLS;
                int rx = k - ry*RCOLS;
                int gy = min(y_lo + ry, 255);
                int gx = min(x_lo + rx, 255);
                st[c][ry][rx] = __ldg(src + gy*WW + gx);
            }
        }
    }
    __syncthreads();

    int lrow = tid >> 3;
    int lcol0 = (tid & 7) << 2;
    int h = h0t + lrow;
    int w = w0t + lcol0;
    float fy = (float)h;
    float* ob = g_xw + (size_t)b*3*HH*WW + h*WW + w;
    float4 acc[3];
    #pragma unroll
    for (int k = 0; k < 4; k++) {
        float fx = (float)(w + k);
        float sx = m[0]*fx + m[1]*fy + m[2];
        float sy = m[3]*fx + m[4]*fy + m[5];
        float cxs = fminf(fmaxf(sx, 0.f), 255.f);
        float cys = fminf(fmaxf(sy, 0.f), 255.f);
        float cx0f = floorf(cxs), cy0f = floorf(cys);
        int cx0 = (int)cx0f, cy0 = (int)cy0f;
        float cwx = cxs - cx0f, cwy = cys - cy0f;
        float w00 = (1.f-cwy)*(1.f-cwx), w01 = (1.f-cwy)*cwx;
        float w10 = cwy*(1.f-cwx),       w11 = cwy*cwx;
        int ix = cx0 - x_lo, iy = cy0 - y_lo;
        // clamped duplicates in the staged region make ix+1/iy+1 value-identical
        // to min(+1,255)-clamped indices
        #pragma unroll
        for (int c = 0; c < 3; c++) {
            float v = st[c][iy][ix]*w00    + st[c][iy][ix+1]*w01
                    + st[c][iy+1][ix]*w10  + st[c][iy+1][ix+1]*w11;
            ((float*)&acc[c])[k] = v;
        }
    }
    #pragma unroll
    for (int c = 0; c < 3; c++)
        *(float4*)(ob + c*HH*WW) = acc[c];
}

// ============================================================================
// K2: crop resample (4 px/thread, scattered — proven) + brightness-gray partials
// ============================================================================
__global__ void __launch_bounds__(256) crop_kernel(CropP P) {
    int b = blockIdx.y;
    int pix0 = (blockIdx.x * 256 + threadIdx.x) * 4;
    int x0 = g_crop[b*3+0], y0 = g_crop[b*3+1], s = g_crop[b*3+2];
    float sf = (float)s / (float)(IMGS - 1);
    const float* xwb = g_xw + (size_t)b*3*HH*WW;
    float fb = P.fb[b];
    float gray = 0.f;
    float4 acc[3];
    #pragma unroll
    for (int k = 0; k < 4; k++) {
        int pix = pix0 + k;
        int vrow = pix / IMGS, ucol = pix % IMGS;
        float xs = (float)x0 + sf * (float)ucol;
        float ys = (float)y0 + sf * (float)vrow;
        xs = fminf(fmaxf(xs, 0.f), 255.f);
        ys = fminf(fmaxf(ys, 0.f), 255.f);
        float x0f = floorf(xs), y0f = floorf(ys);
        int xi = (int)x0f, yi = (int)y0f;
        float wx = xs - x0f, wy = ys - y0f;
        int x1 = min(xi + 1, 255), y1 = min(yi + 1, 255);
        float w00 = (1.f-wy)*(1.f-wx), w01 = (1.f-wy)*wx;
        float w10 = wy*(1.f-wx),       w11 = wy*wx;
        #pragma unroll
        for (int c = 0; c < 3; c++) {
            const float* img = xwb + c*HH*WW;
            float v = __ldg(img + yi*WW + xi)*w00 + __ldg(img + yi*WW + x1)*w01
                    + __ldg(img + y1*WW + xi)*w10 + __ldg(img + y1*WW + x1)*w11;
            ((float*)&acc[c])[k] = v;
            float yv = fminf(fmaxf(v * fb, 0.f), 1.f);
            gray += (c == 0 ? 0.299f : (c == 1 ? 0.587f : 0.114f)) * yv;
        }
    }
    float* ob = g_xc + (size_t)b*3*NPIX + pix0;
    #pragma unroll
    for (int c = 0; c < 3; c++)
        *(float4*)(ob + c*NPIX) = acc[c];

    __shared__ float sred[256];
    sred[threadIdx.x] = gray;
    __syncthreads();
    for (int stride = 128; stride > 0; stride >>= 1) {
        if (threadIdx.x < stride) sred[threadIdx.x] += sred[threadIdx.x + stride];
        __syncthreads();
    }
    if (threadIdx.x == 0) g_partial[b*NBLK + blockIdx.x] = sred[0];
}

// ============================================================================
// K3: fused mean-reduce + color jitter + SEPARABLE 3x9 blur + clip
// ============================================================================
__device__ __forceinline__ void jitter_px(float r0, float g0, float b0,
                                          float fb, float fc, float fs, float fh,
                                          float mean, int ap,
                                          float& ro, float& go, float& bo) {
    if (!ap) { ro = r0; go = g0; bo = b0; return; }
    float r = fminf(fmaxf(r0*fb, 0.f), 1.f);
    float g = fminf(fmaxf(g0*fb, 0.f), 1.f);
    float bl = fminf(fmaxf(b0*fb, 0.f), 1.f);
    r  = fminf(fmaxf(fc*r  + (1.f-fc)*mean, 0.f), 1.f);
    g  = fminf(fmaxf(fc*g  + (1.f-fc)*mean, 0.f), 1.f);
    bl = fminf(fmaxf(fc*bl + (1.f-fc)*mean, 0.f), 1.f);
    float gray = 0.299f*r + 0.587f*g + 0.114f*bl;
    r  = fminf(fmaxf(fs*r  + (1.f-fs)*gray, 0.f), 1.f);
    g  = fminf(fmaxf(fs*g  + (1.f-fs)*gray, 0.f), 1.f);
    bl = fminf(fmaxf(fs*bl + (1.f-fs)*gray, 0.f), 1.f);
    float maxc = fmaxf(r, fmaxf(g, bl));
    float minc = fminf(r, fminf(g, bl));
    float d = maxc - minc;
    const float eps = 1e-8f;
    float s_ = d / fmaxf(maxc, eps);
    float dd = fmaxf(d, eps);
    float h;
    if (maxc == r) {
        float t = (g - bl) / dd;
        h = t - floorf(t / 6.f) * 6.f;
    } else if (maxc == g) {
        h = (bl - r) / dd + 2.f;
    } else {
        h = (r - g) / dd + 4.f;
    }
    h = h / 6.f;
    if (d <= eps) h = 0.f;
    h += fh;
    float hm = h - floorf(h);
    float h6 = hm * 6.f;
    float fi = floorf(h6);
    float f = h6 - fi;
    float v = maxc;
    float pq = v * (1.f - s_);
    float q = v * (1.f - s_*f);
    float t2 = v * (1.f - s_*(1.f - f));
    int i = ((int)fi) % 6;
    float rr, gg, bb;
    switch (i) {
        case 0:  rr = v;  gg = t2; bb = pq; break;
        case 1:  rr = q;  gg = v;  bb = pq; break;
        case 2:  rr = pq; gg = v;  bb = t2; break;
        case 3:  rr = pq; gg = q;  bb = v;  break;
        case 4:  rr = t2; gg = pq; bb = v;  break;
        default: rr = v;  gg = pq; bb = q;  break;
    }
    ro = fminf(fmaxf(rr, 0.f), 1.f);
    go = fminf(fmaxf(gg, 0.f), 1.f);
    bo = fminf(fmaxf(bb, 0.f), 1.f);
}

#define TILE_H 14
#define HALO_H (TILE_H + 2)  /* 16 */
#define HALO_W (IMGS + 8)    /* 232 */

__global__ void __launch_bounds__(256) jb_kernel(JitP jp, BlurP bp, float* __restrict__ out) {
    int b = blockIdx.y;
    int ty0 = blockIdx.x * TILE_H;
    int tid = threadIdx.x;
    __shared__ float tile[3][HALO_H][HALO_W];
    __shared__ float red[256];

    red[tid] = (tid < NBLK) ? g_partial[b*NBLK + tid] : 0.f;
    __syncthreads();
    for (int stride = 128; stride > 0; stride >>= 1) {
        if (tid < stride) red[tid] += red[tid + stride];
        __syncthreads();
    }
    float mean = red[0] / (float)NPIX;
    __syncthreads();

    float fb = jp.fb[b], fc = jp.fc[b], fs = jp.fs[b], fh = jp.fhue[b];
    int apj = jp.ap[b];
    const float* xb = g_xc + (size_t)b*3*NPIX;

    for (int k = tid; k < HALO_H*HALO_W; k += 256) {
        int hr = k / HALO_W, hc = k % HALO_W;
        int gy = ty0 + hr - 1;
        gy = (gy < 0) ? -gy : ((gy > IMGS-1) ? 2*(IMGS-1) - gy : gy);
        int gx = hc - 4;
        gx = (gx < 0) ? -gx : ((gx > IMGS-1) ? 2*(IMGS-1) - gx : gx);
        int pix = gy*IMGS + gx;
        float r0 = __ldg(xb + pix);
        float g0 = __ldg(xb + NPIX + pix);
        float b0 = __ldg(xb + 2*NPIX + pix);
        float ro, go, bo;
        jitter_px(r0, g0, b0, fb, fc, fs, fh, mean, apj, ro, go, bo);
        tile[0][hr][hc] = ro;
        tile[1][hr][hc] = go;
        tile[2][hr][hc] = bo;
    }
    __syncthreads();

    int apb = bp.ap[b];

    if (apb) {
        // separable blur: thread = output column, rolling horizontal sums
        if (tid < IMGS) {
            int c = tid;
            float kyv0 = bp.ky[b][0], kyv1 = bp.ky[b][1], kyv2 = bp.ky[b][2];
            float kxv[9];
            #pragma unroll
            for (int i = 0; i < 9; i++) kxv[i] = bp.kx[b][i];

            float h0[3], h1[3];
            #pragma unroll
            for (int ch = 0; ch < 3; ch++) {
                float ra = 0.f;
                #pragma unroll
                for (int dx = 0; dx < 9; dx++) ra += kxv[dx] * tile[ch][0][c+dx];
                h0[ch] = ra;
                ra = 0.f;
                #pragma unroll
                for (int dx = 0; dx < 9; dx++) ra += kxv[dx] * tile[ch][1][c+dx];
                h1[ch] = ra;
            }
            float* ob = out + (size_t)b*3*NPIX + ty0*IMGS + c;
            for (int r = 0; r < TILE_H; r++) {
                #pragma unroll
                for (int ch = 0; ch < 3; ch++) {
                    float ra = 0.f;
                    #pragma unroll
                    for (int dx = 0; dx < 9; dx++) ra += kxv[dx] * tile[ch][r+2][c+dx];
                    float acc = kyv0 * h0[ch];
                    acc += kyv1 * h1[ch];
                    acc += kyv2 * ra;
                    h0[ch] = h1[ch];
                    h1[ch] = ra;
                    float o = fminf(fmaxf(acc, 0.f), 1.f);
                    ob[ch*NPIX + r*IMGS] = o;
                }
            }
        }
    } else {
        for (int t = tid; t < TILE_H*IMGS; t += 256) {
            int r = t / IMGS, c = t % IMGS;
            #pragma unroll
            for (int ch = 0; ch < 3; ch++) {
                float o = fminf(fmaxf(tile[ch][r+1][c+4], 0.f), 1.f);
                out[(size_t)b*3*NPIX + ch*NPIX + (ty0+r)*IMGS + c] = o;
            }
        }
    }
}

// ============================================================================
// Host: JAX threefry2x32 (partitionable mode)
// ============================================================================
static inline uint32_t rotl32(uint32_t v, int s) { return (v << s) | (v >> (32 - s)); }

static void tf2x32(uint32_t k0, uint32_t k1, uint32_t x0, uint32_t x1,
                   uint32_t* o0, uint32_t* o1) {
    uint32_t ks2 = k0 ^ k1 ^ 0x1BD11BDAu;
    x0 += k0; x1 += k1;
    static const int R[2][4] = {{13,15,26,6},{17,29,16,24}};
    const uint32_t inj0[5] = {k1, ks2, k0, k1, ks2};
    const uint32_t inj1[5] = {ks2, k0, k1, ks2, k0};
    for (int g = 0; g < 5; g++) {
        for (int r = 0; r < 4; r++) {
            x0 += x1; x1 = rotl32(x1, R[g & 1][r]); x1 ^= x0;
        }
        x0 += inj0[g];
        x1 += inj1[g] + (uint32_t)(g + 1);
    }
    *o0 = x0; *o1 = x1;
}

static float h_u01(uint32_t k0, uint32_t k1, uint32_t i) {
    uint32_t a, b;
    tf2x32(k0, k1, 0u, i, &a, &b);
    uint32_t bits = a ^ b;
    uint32_t fbits = (bits >> 9) | 0x3f800000u;
    float f;
    memcpy(&f, &fbits, 4);
    return f - 1.0f;
}
static float h_uni(uint32_t k0, uint32_t k1, uint32_t i, float mn, float mx) {
    float u = h_u01(k0, k1, i);
    float v = u * (mx - mn) + mn;
    return (v < mn) ? mn : v;
}
static void h_split(uint32_t k0, uint32_t k1, int n, uint32_t out[][2]) {
    for (int i = 0; i < n; i++)
        tf2x32(k0, k1, 0u, (uint32_t)i, &out[i][0], &out[i][1]);
}

extern "C" void kernel_launch(void* const* d_in, const int* in_sizes, int n_in,
                              void* d_out, int out_size) {
    const float* x = (const float*)d_in[0];
    float* out = (float*)d_out;
    const float PI_F = 3.14159265358979323846f;

    uint32_t K3_[3][2];
    h_split(0u, 42u, 3, K3_);

    // ---- affine params ----
    uint32_t ka[6][2];
    h_split(K3_[0][0], K3_[0][1], 6, ka);
    static WarpP wp;
    for (int b = 0; b < BB; b++) {
        bool fhl = h_u01(ka[0][0], ka[0][1], b) < 0.5f;
        bool fvl = h_u01(ka[1][0], ka[1][1], b) < 0.5f;
        float ang = h_uni(ka[2][0], ka[2][1], b, -20.f, 20.f) * (PI_F / 180.f);
        float sc  = h_uni(ka[3][0], ka[3][1], b, 0.85f, 1.15f);
        float tx  = h_uni(ka[4][0], ka[4][1], b, -0.1f, 0.1f) * 256.f;
        float ty  = h_uni(ka[5][0], ka[5][1], b, -0.1f, 0.1f) * 256.f;
        float ca = cosf(ang) * sc, sa = sinf(ang) * sc;
        float a = ca, b2 = -sa, c2 = sa, d = ca;
        float cx = 127.5f, cy = 127.5f;
        float m02 = tx + cx - a*cx - b2*cy;
        float m12 = ty + cy - c2*cx - d*cy;
        float fxs = fhl ? -1.f : 1.f, fys = fvl ? -1.f : 1.f;
        float F02 = fhl ? 255.f : 0.f, F12 = fvl ? 255.f : 0.f;
        float M00 = a*fxs,  M01 = b2*fys, M02 = a*F02 + b2*F12 + m02;
        float M10 = c2*fxs, M11 = d*fys,  M12 = c2*F02 + d*F12 + m12;
        double det = (double)M00*(double)M11 - (double)M01*(double)M10;
        wp.inv[b][0] = (float)( (double)M11 / det);
        wp.inv[b][1] = (float)(-(double)M01 / det);
        wp.inv[b][2] = (float)(((double)M01*(double)M12 - (double)M02*(double)M11) / det);
        wp.inv[b][3] = (float)(-(double)M10 / det);
        wp.inv[b][4] = (float)( (double)M00 / det);
        wp.inv[b][5] = (float)(((double)M02*(double)M10 - (double)M00*(double)M12) / det);
    }

    // ---- color jitter params ----
    uint32_t kc5[5][2];
    h_split(K3_[1][0], K3_[1][1], 5, kc5);
    static CropP cp;
    static JitP jp;
    for (int b = 0; b < BB; b++) {
        float fb = h_uni(kc5[0][0], kc5[0][1], b, 0.7f, 1.3f);
        cp.fb[b] = fb; jp.fb[b] = fb;
        jp.fc[b]   = h_uni(kc5[1][0], kc5[1][1], b, 0.7f, 1.3f);
        jp.fs[b]   = h_uni(kc5[2][0], kc5[2][1], b, 0.7f, 1.3f);
        jp.fhue[b] = h_uni(kc5[3][0], kc5[3][1], b, -0.15f, 0.15f);
        jp.ap[b]   = (h_u01(kc5[4][0], kc5[4][1], b) < 0.7f) ? 1 : 0;
    }

    // ---- blur params ----
    uint32_t kb2[2][2];
    h_split(K3_[2][0], K3_[2][1], 2, kb2);
    static BlurP bp;
    for (int b = 0; b < BB; b++) {
        float sig = h_uni(kb2[0][0], kb2[0][1], b, 0.1f, 2.0f);
        float s2 = 2.f * sig * sig;
        float wy[3], wxv[9];
        float sumy = 0.f, sumx = 0.f;
        for (int i = 0; i < 3; i++) {
            float xk = (float)i - 1.f;
            wy[i] = expf(-(xk*xk) / s2);
            sumy += wy[i];
        }
        for (int i = 0; i < 9; i++) {
            float xk = (float)i - 4.f;
            wxv[i] = expf(-(xk*xk) / s2);
            sumx += wxv[i];
        }
        for (int i = 0; i < 3; i++) bp.ky[b][i] = wy[i] / sumy;
        for (int i = 0; i < 9; i++) bp.kx[b][i] = wxv[i] / sumx;
        bp.ap[b] = (h_u01(kb2[1][0], kb2[1][1], b) < 0.5f) ? 1 : 0;
    }

    // ---- launches ----
    warp_maxsq_kernel<<<BB + TILEBLKS, 256>>>(x, wp);
    dim3 g3(NBLK, BB);
    crop_kernel<<<g3, 256>>>(cp);
    dim3 g4(IMGS / TILE_H, BB);
    jb_kernel<<<g4, 256>>>(jp, bp, out);
}

// round 15
// speedup vs baseline: 1.0739x; 1.0739x over previous
#include <cuda_runtime.h>
#include <cstdint>
#include <cstring>
#include <cmath>

#define BB 64
#define HH 256
#define WW 256
#define IMGS 224
#define NPIX (IMGS*IMGS)   /* 50176 */
#define NBLK 49            /* 50176 / (256*4) */
#define TILEBLKS 4096      /* 64 images * 64 tiles (8x8 tiles of 32x32) */

#define RROWS 51           /* staged source rows */
#define RCOLS 56           /* staged source cols (x_lo aligned to 4) */
#define RPITCH 60          /* smem pitch in floats (16B-aligned rows) */
#define NV4 14             /* float4 per staged row */

// ---------------- device scratch (static globals; no allocs) ----------------
__device__ float g_xw[BB*3*HH*WW];     // warped 256x256 (planar)
__device__ float g_xc[BB*3*NPIX];      // cropped 224x224 (planar)
__device__ float g_partial[BB*NBLK];   // gray partial sums

// ---------------- parameter structs (passed by value) ----------------
struct WarpP { float inv[BB][6]; unsigned long long tmask[BB]; };
struct CropP { float cx0[BB], cy0[BB], sf[BB], fb[BB]; };
struct JitP  { float fb[BB], fc[BB], fs[BB], fhue[BB]; int ap[BB]; };
struct BlurP { float ky[BB][3]; float kx[BB][9]; int ap[BB]; };

// ============================================================================
// K1: affine warp, smem-tiled 32x32 output tiles; tiles outside the host-
//     computed crop window bitmask return immediately.
// ============================================================================
__global__ void __launch_bounds__(256) warp_kernel(const float* __restrict__ x, WarpP P) {
    __shared__ __align__(16) float st[3][RROWS][RPITCH];   // 36.7KB

    int tb = blockIdx.x;
    int b = tb >> 6;
    int tile = tb & 63;
    if (!((P.tmask[b] >> tile) & 1ull)) return;

    int w0t = (tile & 7) << 5;
    int h0t = (tile >> 3) << 5;
    const float* m = P.inv[b];
    int tid = threadIdx.x;

    // bbox of clamped source coords over the tile's 4 corners (affine => hull)
    float f_w0 = (float)w0t, f_w1 = (float)(w0t + 31);
    float f_h0 = (float)h0t, f_h1 = (float)(h0t + 31);
    float sx00 = m[0]*f_w0 + m[1]*f_h0 + m[2];
    float sx10 = m[0]*f_w1 + m[1]*f_h0 + m[2];
    float sx01 = m[0]*f_w0 + m[1]*f_h1 + m[2];
    float sx11 = m[0]*f_w1 + m[1]*f_h1 + m[2];
    float sy00 = m[3]*f_w0 + m[4]*f_h0 + m[5];
    float sy10 = m[3]*f_w1 + m[4]*f_h0 + m[5];
    float sy01 = m[3]*f_w0 + m[4]*f_h1 + m[5];
    float sy11 = m[3]*f_w1 + m[4]*f_h1 + m[5];
    float cminx = fminf(fminf(sx00, sx10), fminf(sx01, sx11));
    float cminy = fminf(fminf(sy00, sy10), fminf(sy01, sy11));
    cminx = fminf(fmaxf(cminx, 0.f), 255.f);
    cminy = fminf(fmaxf(cminy, 0.f), 255.f);
    int x_lo = (max((int)floorf(cminx) - 1, 0)) & ~3;     // 4-aligned
    int y_lo = max((int)floorf(cminy) - 1, 0);

    const float* xb = x + (size_t)b*3*HH*WW;
    if (x_lo + (RCOLS - 1) <= 255) {
        // interior fast path: float4 staging (no column clamp needed)
        #pragma unroll
        for (int c = 0; c < 3; c++) {
            const float4* src = (const float4*)(xb + c*HH*WW + x_lo);
            float4* dst = (float4*)&st[c][0][0];
            for (int k = tid; k < RROWS*NV4; k += 256) {
                int ry = k / NV4;
                int rx4 = k - ry*NV4;
                int gy = min(y_lo + ry, 255);
                dst[ry*(RPITCH/4) + rx4] = __ldg(src + gy*(WW/4) + rx4);
            }
        }
    } else {
        // edge path: scalar staging with per-element clamp (duplicates edge col)
        #pragma unroll
        for (int c = 0; c < 3; c++) {
            const float* src = xb + c*HH*WW;
            for (int k = tid; k < RROWS*RCOLS; k += 256) {
                int ry = k / RCOLS;
                int rx = k - ry*RCOLS;
                int gy = min(y_lo + ry, 255);
                int gx = min(x_lo + rx, 255);
                st[c][ry][rx] = __ldg(src + gy*WW + gx);
            }
        }
    }
    __syncthreads();

    int lrow = tid >> 3;
    int lcol0 = (tid & 7) << 2;
    int h = h0t + lrow;
    int w = w0t + lcol0;
    float fy = (float)h;
    float* ob = g_xw + (size_t)b*3*HH*WW + h*WW + w;
    float4 acc[3];
    #pragma unroll
    for (int k = 0; k < 4; k++) {
        float fx = (float)(w + k);
        float sx = m[0]*fx + m[1]*fy + m[2];
        float sy = m[3]*fx + m[4]*fy + m[5];
        float cxs = fminf(fmaxf(sx, 0.f), 255.f);
        float cys = fminf(fmaxf(sy, 0.f), 255.f);
        float cx0f = floorf(cxs), cy0f = floorf(cys);
        int cx0 = (int)cx0f, cy0 = (int)cy0f;
        float cwx = cxs - cx0f, cwy = cys - cy0f;
        float w00 = (1.f-cwy)*(1.f-cwx), w01 = (1.f-cwy)*cwx;
        float w10 = cwy*(1.f-cwx),       w11 = cwy*cwx;
        int ix = cx0 - x_lo, iy = cy0 - y_lo;
        // clamped duplicates in the staged region make ix+1/iy+1 value-identical
        // to min(+1,255)-clamped indices
        #pragma unroll
        for (int c = 0; c < 3; c++) {
            float v = st[c][iy][ix]*w00    + st[c][iy][ix+1]*w01
                    + st[c][iy+1][ix]*w10  + st[c][iy+1][ix+1]*w11;
            ((float*)&acc[c])[k] = v;
        }
    }
    #pragma unroll
    for (int c = 0; c < 3; c++)
        *(float4*)(ob + c*HH*WW) = acc[c];
}

// ============================================================================
// K2: crop resample (4 px/thread, scattered — proven) + brightness-gray partials
// ============================================================================
__global__ void __launch_bounds__(256) crop_kernel(CropP P) {
    int b = blockIdx.y;
    int pix0 = (blockIdx.x * 256 + threadIdx.x) * 4;
    float fx0 = P.cx0[b], fy0 = P.cy0[b], sf = P.sf[b];
    const float* xwb = g_xw + (size_t)b*3*HH*WW;
    float fb = P.fb[b];
    float gray = 0.f;
    float4 acc[3];
    #pragma unroll
    for (int k = 0; k < 4; k++) {
        int pix = pix0 + k;
        int vrow = pix / IMGS, ucol = pix % IMGS;
        float xs = fx0 + sf * (float)ucol;
        float ys = fy0 + sf * (float)vrow;
        xs = fminf(fmaxf(xs, 0.f), 255.f);
        ys = fminf(fmaxf(ys, 0.f), 255.f);
        float x0f = floorf(xs), y0f = floorf(ys);
        int xi = (int)x0f, yi = (int)y0f;
        float wx = xs - x0f, wy = ys - y0f;
        int x1 = min(xi + 1, 255), y1 = min(yi + 1, 255);
        float w00 = (1.f-wy)*(1.f-wx), w01 = (1.f-wy)*wx;
        float w10 = wy*(1.f-wx),       w11 = wy*wx;
        #pragma unroll
        for (int c = 0; c < 3; c++) {
            const float* img = xwb + c*HH*WW;
            float v = __ldg(img + yi*WW + xi)*w00 + __ldg(img + yi*WW + x1)*w01
                    + __ldg(img + y1*WW + xi)*w10 + __ldg(img + y1*WW + x1)*w11;
            ((float*)&acc[c])[k] = v;
            float yv = fminf(fmaxf(v * fb, 0.f), 1.f);
            gray += (c == 0 ? 0.299f : (c == 1 ? 0.587f : 0.114f)) * yv;
        }
    }
    float* ob = g_xc + (size_t)b*3*NPIX + pix0;
    #pragma unroll
    for (int c = 0; c < 3; c++)
        *(float4*)(ob + c*NPIX) = acc[c];

    __shared__ float sred[256];
    sred[threadIdx.x] = gray;
    __syncthreads();
    for (int stride = 128; stride > 0; stride >>= 1) {
        if (threadIdx.x < stride) sred[threadIdx.x] += sred[threadIdx.x + stride];
        __syncthreads();
    }
    if (threadIdx.x == 0) g_partial[b*NBLK + blockIdx.x] = sred[0];
}

// ============================================================================
// K3: fused mean-reduce + color jitter + SEPARABLE 3x9 blur + clip
// ============================================================================
__device__ __forceinline__ void jitter_px(float r0, float g0, float b0,
                                          float fb, float fc, float fs, float fh,
                                          float mean, int ap,
                                          float& ro, float& go, float& bo) {
    if (!ap) { ro = r0; go = g0; bo = b0; return; }
    float r = fminf(fmaxf(r0*fb, 0.f), 1.f);
    float g = fminf(fmaxf(g0*fb, 0.f), 1.f);
    float bl = fminf(fmaxf(b0*fb, 0.f), 1.f);
    r  = fminf(fmaxf(fc*r  + (1.f-fc)*mean, 0.f), 1.f);
    g  = fminf(fmaxf(fc*g  + (1.f-fc)*mean, 0.f), 1.f);
    bl = fminf(fmaxf(fc*bl + (1.f-fc)*mean, 0.f), 1.f);
    float gray = 0.299f*r + 0.587f*g + 0.114f*bl;
    r  = fminf(fmaxf(fs*r  + (1.f-fs)*gray, 0.f), 1.f);
    g  = fminf(fmaxf(fs*g  + (1.f-fs)*gray, 0.f), 1.f);
    bl = fminf(fmaxf(fs*bl + (1.f-fs)*gray, 0.f), 1.f);
    float maxc = fmaxf(r, fmaxf(g, bl));
    float minc = fminf(r, fminf(g, bl));
    float d = maxc - minc;
    const float eps = 1e-8f;
    float s_ = d / fmaxf(maxc, eps);
    float dd = fmaxf(d, eps);
    float h;
    if (maxc == r) {
        float t = (g - bl) / dd;
        h = t - floorf(t / 6.f) * 6.f;
    } else if (maxc == g) {
        h = (bl - r) / dd + 2.f;
    } else {
        h = (r - g) / dd + 4.f;
    }
    h = h / 6.f;
    if (d <= eps) h = 0.f;
    h += fh;
    float hm = h - floorf(h);
    float h6 = hm * 6.f;
    float fi = floorf(h6);
    float f = h6 - fi;
    float v = maxc;
    float pq = v * (1.f - s_);
    float q = v * (1.f - s_*f);
    float t2 = v * (1.f - s_*(1.f - f));
    int i = ((int)fi) % 6;
    float rr, gg, bb;
    switch (i) {
        case 0:  rr = v;  gg = t2; bb = pq; break;
        case 1:  rr = q;  gg = v;  bb = pq; break;
        case 2:  rr = pq; gg = v;  bb = t2; break;
        case 3:  rr = pq; gg = q;  bb = v;  break;
        case 4:  rr = t2; gg = pq; bb = v;  break;
        default: rr = v;  gg = pq; bb = q;  break;
    }
    ro = fminf(fmaxf(rr, 0.f), 1.f);
    go = fminf(fmaxf(gg, 0.f), 1.f);
    bo = fminf(fmaxf(bb, 0.f), 1.f);
}

#define TILE_H 14
#define HALO_H (TILE_H + 2)  /* 16 */
#define HALO_W (IMGS + 8)    /* 232 */

__global__ void __launch_bounds__(256) jb_kernel(JitP jp, BlurP bp, float* __restrict__ out) {
    int b = blockIdx.y;
    int ty0 = blockIdx.x * TILE_H;
    int tid = threadIdx.x;
    __shared__ float tile[3][HALO_H][HALO_W];
    __shared__ float red[256];

    red[tid] = (tid < NBLK) ? g_partial[b*NBLK + tid] : 0.f;
    __syncthreads();
    for (int stride = 128; stride > 0; stride >>= 1) {
        if (tid < stride) red[tid] += red[tid + stride];
        __syncthreads();
    }
    float mean = red[0] / (float)NPIX;
    __syncthreads();

    float fb = jp.fb[b], fc = jp.fc[b], fs = jp.fs[b], fh = jp.fhue[b];
    int apj = jp.ap[b];
    const float* xb = g_xc + (size_t)b*3*NPIX;

    for (int k = tid; k < HALO_H*HALO_W; k += 256) {
        int hr = k / HALO_W, hc = k % HALO_W;
        int gy = ty0 + hr - 1;
        gy = (gy < 0) ? -gy : ((gy > IMGS-1) ? 2*(IMGS-1) - gy : gy);
        int gx = hc - 4;
        gx = (gx < 0) ? -gx : ((gx > IMGS-1) ? 2*(IMGS-1) - gx : gx);
        int pix = gy*IMGS + gx;
        float r0 = __ldg(xb + pix);
        float g0 = __ldg(xb + NPIX + pix);
        float b0 = __ldg(xb + 2*NPIX + pix);
        float ro, go, bo;
        jitter_px(r0, g0, b0, fb, fc, fs, fh, mean, apj, ro, go, bo);
        tile[0][hr][hc] = ro;
        tile[1][hr][hc] = go;
        tile[2][hr][hc] = bo;
    }
    __syncthreads();

    int apb = bp.ap[b];

    if (apb) {
        // separable blur: thread = output column, rolling horizontal sums
        if (tid < IMGS) {
            int c = tid;
            float kyv0 = bp.ky[b][0], kyv1 = bp.ky[b][1], kyv2 = bp.ky[b][2];
            float kxv[9];
            #pragma unroll
            for (int i = 0; i < 9; i++) kxv[i] = bp.kx[b][i];

            float h0[3], h1[3];
            #pragma unroll
            for (int ch = 0; ch < 3; ch++) {
                float ra = 0.f;
                #pragma unroll
                for (int dx = 0; dx < 9; dx++) ra += kxv[dx] * tile[ch][0][c+dx];
                h0[ch] = ra;
                ra = 0.f;
                #pragma unroll
                for (int dx = 0; dx < 9; dx++) ra += kxv[dx] * tile[ch][1][c+dx];
                h1[ch] = ra;
            }
            float* ob = out + (size_t)b*3*NPIX + ty0*IMGS + c;
            for (int r = 0; r < TILE_H; r++) {
                #pragma unroll
                for (int ch = 0; ch < 3; ch++) {
                    float ra = 0.f;
                    #pragma unroll
                    for (int dx = 0; dx < 9; dx++) ra += kxv[dx] * tile[ch][r+2][c+dx];
                    float acc = kyv0 * h0[ch];
                    acc += kyv1 * h1[ch];
                    acc += kyv2 * ra;
                    h0[ch] = h1[ch];
                    h1[ch] = ra;
                    float o = fminf(fmaxf(acc, 0.f), 1.f);
                    ob[ch*NPIX + r*IMGS] = o;
                }
            }
        }
    } else {
        for (int t = tid; t < TILE_H*IMGS; t += 256) {
            int r = t / IMGS, c = t % IMGS;
            #pragma unroll
            for (int ch = 0; ch < 3; ch++) {
                float o = fminf(fmaxf(tile[ch][r+1][c+4], 0.f), 1.f);
                out[(size_t)b*3*NPIX + ch*NPIX + (ty0+r)*IMGS + c] = o;
            }
        }
    }
}

// ============================================================================
// Host: JAX threefry2x32 (partitionable mode) + host-side max-square DP
// ============================================================================
static inline uint32_t rotl32(uint32_t v, int s) { return (v << s) | (v >> (32 - s)); }

static void tf2x32(uint32_t k0, uint32_t k1, uint32_t x0, uint32_t x1,
                   uint32_t* o0, uint32_t* o1) {
    uint32_t ks2 = k0 ^ k1 ^ 0x1BD11BDAu;
    x0 += k0; x1 += k1;
    static const int R[2][4] = {{13,15,26,6},{17,29,16,24}};
    const uint32_t inj0[5] = {k1, ks2, k0, k1, ks2};
    const uint32_t inj1[5] = {ks2, k0, k1, ks2, k0};
    for (int g = 0; g < 5; g++) {
        for (int r = 0; r < 4; r++) {
            x0 += x1; x1 = rotl32(x1, R[g & 1][r]); x1 ^= x0;
        }
        x0 += inj0[g];
        x1 += inj1[g] + (uint32_t)(g + 1);
    }
    *o0 = x0; *o1 = x1;
}

static float h_u01(uint32_t k0, uint32_t k1, uint32_t i) {
    uint32_t a, b;
    tf2x32(k0, k1, 0u, i, &a, &b);
    uint32_t bits = a ^ b;
    uint32_t fbits = (bits >> 9) | 0x3f800000u;
    float f;
    memcpy(&f, &fbits, 4);
    return f - 1.0f;
}
static float h_uni(uint32_t k0, uint32_t k1, uint32_t i, float mn, float mx) {
    float u = h_u01(k0, k1, i);
    float v = u * (mx - mn) + mn;
    return (v < mn) ? mn : v;
}
static void h_split(uint32_t k0, uint32_t k1, int n, uint32_t out[][2]) {
    for (int i = 0; i < n; i++)
        tf2x32(k0, k1, 0u, (uint32_t)i, &out[i][0], &out[i][1]);
}

// host coverage: same logic as the device version; double precision dominates
// the ~1e-7 float noise while the >0.5 decision margin is ~1e-2.
static int h_cov(const float* m, double fx, double fy) {
    double sx = (double)m[0]*fx + (double)m[1]*fy + (double)m[2];
    double sy = (double)m[3]*fx + (double)m[4]*fy + (double)m[5];
    double x0f = floor(sx), y0f = floor(sy);
    int xi = (int)x0f, yi = (int)y0f;
    double wx = sx - x0f, wy = sy - y0f;
    double i00 = (yi   >= 0 && yi   < HH && xi   >= 0 && xi   < WW) ? 1.0 : 0.0;
    double i01 = (yi   >= 0 && yi   < HH && xi+1 >= 0 && xi+1 < WW) ? 1.0 : 0.0;
    double i10 = (yi+1 >= 0 && yi+1 < HH && xi   >= 0 && xi   < WW) ? 1.0 : 0.0;
    double i11 = (yi+1 >= 0 && yi+1 < HH && xi+1 >= 0 && xi+1 < WW) ? 1.0 : 0.0;
    double cov = i00*(1.0-wy)*(1.0-wx) + i01*(1.0-wy)*wx + i10*wy*(1.0-wx) + i11*wy*wx;
    return cov > 0.5 ? 1 : 0;
}

extern "C" void kernel_launch(void* const* d_in, const int* in_sizes, int n_in,
                              void* d_out, int out_size) {
    const float* x = (const float*)d_in[0];
    float* out = (float*)d_out;
    const float PI_F = 3.14159265358979323846f;

    uint32_t K3_[3][2];
    h_split(0u, 42u, 3, K3_);

    // ---- affine params ----
    uint32_t ka[6][2];
    h_split(K3_[0][0], K3_[0][1], 6, ka);
    static WarpP wp;
    for (int b = 0; b < BB; b++) {
        bool fhl = h_u01(ka[0][0], ka[0][1], b) < 0.5f;
        bool fvl = h_u01(ka[1][0], ka[1][1], b) < 0.5f;
        float ang = h_uni(ka[2][0], ka[2][1], b, -20.f, 20.f) * (PI_F / 180.f);
        float sc  = h_uni(ka[3][0], ka[3][1], b, 0.85f, 1.15f);
        float tx  = h_uni(ka[4][0], ka[4][1], b, -0.1f, 0.1f) * 256.f;
        float ty  = h_uni(ka[5][0], ka[5][1], b, -0.1f, 0.1f) * 256.f;
        float ca = cosf(ang) * sc, sa = sinf(ang) * sc;
        float a = ca, b2 = -sa, c2 = sa, d = ca;
        float cx = 127.5f, cy = 127.5f;
        float m02 = tx + cx - a*cx - b2*cy;
        float m12 = ty + cy - c2*cx - d*cy;
        float fxs = fhl ? -1.f : 1.f, fys = fvl ? -1.f : 1.f;
        float F02 = fhl ? 255.f : 0.f, F12 = fvl ? 255.f : 0.f;
        float M00 = a*fxs,  M01 = b2*fys, M02 = a*F02 + b2*F12 + m02;
        float M10 = c2*fxs, M11 = d*fys,  M12 = c2*F02 + d*F12 + m12;
        double det = (double)M00*(double)M11 - (double)M01*(double)M10;
        wp.inv[b][0] = (float)( (double)M11 / det);
        wp.inv[b][1] = (float)(-(double)M01 / det);
        wp.inv[b][2] = (float)(((double)M01*(double)M12 - (double)M02*(double)M11) / det);
        wp.inv[b][3] = (float)(-(double)M10 / det);
        wp.inv[b][4] = (float)( (double)M00 / det);
        wp.inv[b][5] = (float)(((double)M02*(double)M10 - (double)M00*(double)M12) / det);
    }

    // ---- host max-square DP (interval-based, same logic as the old device DP) --
    static CropP cp;
    for (int b = 0; b < BB; b++) {
        const float* m = wp.inv[b];
        int L[HH], R[HH];
        for (int t = 0; t < HH; t++) {
            int Lv = 256, Rv = -1;
            for (int j = 0; j < WW; j++) {
                if (h_cov(m, (double)j, (double)t)) { if (j < Lv) Lv = j; Rv = j; }
            }
            L[t] = Lv; R[t] = Rv;
        }
        int bestS = 0, bestI = 0;
        for (int t = 0; t < HH; t++) {
            int bs = 0;
            if (R[t] >= L[t]) {
                int Lmax = L[t], Rmin = R[t];
                int s = 1;
                while (t - s >= 0) {
                    if (L[t-s] > Lmax) Lmax = L[t-s];
                    if (R[t-s] < Rmin) Rmin = R[t-s];
                    if (Rmin - Lmax + 1 >= s + 1) s++;
                    else break;
                }
                bs = s;
            }
            if (bs > bestS) { bestS = bs; bestI = t; }
        }
        int s = bestS, ii = bestI, x0, y0;
        if (s == 0) { x0 = WW/2; y0 = HH/2; s = 1; }
        else {
            int Lmax = -1;
            for (int r = ii - s + 1; r <= ii; r++) if (L[r] > Lmax) Lmax = L[r];
            int jj = Lmax + s - 1;
            x0 = jj + 1 - s; y0 = ii + 1 - s;
        }
        cp.cx0[b] = (float)x0;
        cp.cy0[b] = (float)y0;
        cp.sf[b]  = (float)s / (float)(IMGS - 1);

        // tile bitmask of the crop window (the only region K2 reads)
        int xlo = x0, xhi = x0 + s + 1; if (xhi > 255) xhi = 255;
        int ylo = y0, yhi = y0 + s + 1; if (yhi > 255) yhi = 255;
        unsigned long long mask = 0ull;
        for (int ty = ylo >> 5; ty <= (yhi >> 5); ty++)
            for (int tx = xlo >> 5; tx <= (xhi >> 5); tx++)
                mask |= 1ull << (ty*8 + tx);
        wp.tmask[b] = mask;
    }

    // ---- color jitter params ----
    uint32_t kc5[5][2];
    h_split(K3_[1][0], K3_[1][1], 5, kc5);
    static JitP jp;
    for (int b = 0; b < BB; b++) {
        float fb = h_uni(kc5[0][0], kc5[0][1], b, 0.7f, 1.3f);
        cp.fb[b] = fb; jp.fb[b] = fb;
        jp.fc[b]   = h_uni(kc5[1][0], kc5[1][1], b, 0.7f, 1.3f);
        jp.fs[b]   = h_uni(kc5[2][0], kc5[2][1], b, 0.7f, 1.3f);
        jp.fhue[b] = h_uni(kc5[3][0], kc5[3][1], b, -0.15f, 0.15f);
        jp.ap[b]   = (h_u01(kc5[4][0], kc5[4][1], b) < 0.7f) ? 1 : 0;
    }

    // ---- blur params ----
    uint32_t kb2[2][2];
    h_split(K3_[2][0], K3_[2][1], 2, kb2);
    static BlurP bp;
    for (int b = 0; b < BB; b++) {
        float sig = h_uni(kb2[0][0], kb2[0][1], b, 0.1f, 2.0f);
        float s2 = 2.f * sig * sig;
        float wy[3], wxv[9];
        float sumy = 0.f, sumx = 0.f;
        for (int i = 0; i < 3; i++) {
            float xk = (float)i - 1.f;
            wy[i] = expf(-(xk*xk) / s2);
            sumy += wy[i];
        }
        for (int i = 0; i < 9; i++) {
            float xk = (float)i - 4.f;
            wxv[i] = expf(-(xk*xk) / s2);
            sumx += wxv[i];
        }
        for (int i = 0; i < 3; i++) bp.ky[b][i] = wy[i] / sumy;
        for (int i = 0; i < 9; i++) bp.kx[b][i] = wxv[i] / sumx;
        bp.ap[b] = (h_u01(kb2[1][0], kb2[1][1], b) < 0.5f) ? 1 : 0;
    }

    // ---- launches ----
    warp_kernel<<<TILEBLKS, 256>>>(x, wp);
    dim3 g3(NBLK, BB);
    crop_kernel<<<g3, 256>>>(cp);
    dim3 g4(IMGS / TILE_H, BB);
    jb_kernel<<<g4, 256>>>(jp, bp, out);
}

// round 16
// speedup vs baseline: 1.1180x; 1.0411x over previous
#include <cuda_runtime.h>
#include <cstdint>
#include <cstring>
#include <cmath>

#define BB 64
#define HH 256
#define WW 256
#define IMGS 224
#define NPIX (IMGS*IMGS)   /* 50176 */
#define NBLK 49            /* 50176 / (256*4) */
#define TILEBLKS 4096      /* 64 images * 64 tiles (8x8 tiles of 32x32) */

#define RROWS 51           /* staged source rows (max) */
#define RCOLS 56           /* staged source cols (x_lo aligned to 4) */
#define RPITCH 60          /* smem pitch in floats (16B-aligned rows) */
#define NV4 14             /* float4 per staged row (max) */

// ---------------- device scratch (static globals; no allocs) ----------------
__device__ float g_xw[BB*3*HH*WW];     // warped 256x256 (planar)
__device__ float g_xc[BB*3*NPIX];      // cropped 224x224 (planar)
__device__ float g_partial[BB*NBLK];   // gray partial sums

// ---------------- parameter structs (passed by value) ----------------
struct WarpP { float inv[BB][6]; unsigned long long tmask[BB]; int win[BB][4]; };
struct CropP { float cx0[BB], cy0[BB], sf[BB], fb[BB]; };
struct JitP  { float fb[BB], fc[BB], fs[BB], fhue[BB]; int ap[BB]; };
struct BlurP { float ky[BB][3]; float kx[BB][9]; int ap[BB]; };

// ============================================================================
// K1: affine warp, smem-tiled 32x32 tiles, pixel-granular crop-window clipping
// ============================================================================
__global__ void __launch_bounds__(256) warp_kernel(const float* __restrict__ x, WarpP P) {
    __shared__ __align__(16) float st[3][RROWS][RPITCH];   // 36.7KB

    int tb = blockIdx.x;
    int b = tb >> 6;
    int tile = tb & 63;
    if (!((P.tmask[b] >> tile) & 1ull)) return;

    int w0t = (tile & 7) << 5;
    int h0t = (tile >> 3) << 5;
    const float* m = P.inv[b];
    int tid = threadIdx.x;

    // active sub-rectangle = tile ∩ crop window (non-empty: tmask passed)
    int aw0 = max(w0t, P.win[b][0]), aw1 = min(w0t + 31, P.win[b][1]);
    int ah0 = max(h0t, P.win[b][2]), ah1 = min(h0t + 31, P.win[b][3]);

    // source-coordinate hull over the active subrect corners (affine)
    float f_w0 = (float)aw0, f_w1 = (float)aw1;
    float f_h0 = (float)ah0, f_h1 = (float)ah1;
    float sx00 = m[0]*f_w0 + m[1]*f_h0 + m[2];
    float sx10 = m[0]*f_w1 + m[1]*f_h0 + m[2];
    float sx01 = m[0]*f_w0 + m[1]*f_h1 + m[2];
    float sx11 = m[0]*f_w1 + m[1]*f_h1 + m[2];
    float sy00 = m[3]*f_w0 + m[4]*f_h0 + m[5];
    float sy10 = m[3]*f_w1 + m[4]*f_h0 + m[5];
    float sy01 = m[3]*f_w0 + m[4]*f_h1 + m[5];
    float sy11 = m[3]*f_w1 + m[4]*f_h1 + m[5];
    float cminx = fminf(fminf(sx00, sx10), fminf(sx01, sx11));
    float cmaxx = fmaxf(fmaxf(sx00, sx10), fmaxf(sx01, sx11));
    float cminy = fminf(fminf(sy00, sy10), fminf(sy01, sy11));
    float cmaxy = fmaxf(fmaxf(sy00, sy10), fmaxf(sy01, sy11));
    cminx = fminf(fmaxf(cminx, 0.f), 255.f);
    cmaxx = fminf(fmaxf(cmaxx, 0.f), 255.f);
    cminy = fminf(fmaxf(cminy, 0.f), 255.f);
    cmaxy = fminf(fmaxf(cmaxy, 0.f), 255.f);
    int x_lo = (max((int)floorf(cminx) - 1, 0)) & ~3;     // 4-aligned
    int y_lo = max((int)floorf(cminy) - 1, 0);
    int rows_needed = min(RROWS, (int)floorf(cmaxy) + 3 - y_lo);
    int nv4_needed  = min(NV4, (((int)floorf(cmaxx) + 3 - x_lo) + 3) >> 2);
    if (rows_needed < 1) rows_needed = 1;
    if (nv4_needed < 1) nv4_needed = 1;

    const float* xb = x + (size_t)b*3*HH*WW;
    if (x_lo + (RCOLS - 1) <= 255) {
        // interior fast path: float4 staging (no column clamp needed)
        #pragma unroll
        for (int c = 0; c < 3; c++) {
            const float4* src = (const float4*)(xb + c*HH*WW + x_lo);
            float4* dst = (float4*)&st[c][0][0];
            for (int k = tid; k < rows_needed*nv4_needed; k += 256) {
                int ry = k / nv4_needed;
                int rx4 = k - ry*nv4_needed;
                int gy = min(y_lo + ry, 255);
                dst[ry*(RPITCH/4) + rx4] = __ldg(src + gy*(WW/4) + rx4);
            }
        }
    } else {
        // edge path: scalar staging with per-element clamp (duplicates edge col)
        int cols_needed = nv4_needed * 4;
        #pragma unroll
        for (int c = 0; c < 3; c++) {
            const float* src = xb + c*HH*WW;
            for (int k = tid; k < rows_needed*cols_needed; k += 256) {
                int ry = k / cols_needed;
                int rx = k - ry*cols_needed;
                int gy = min(y_lo + ry, 255);
                int gx = min(x_lo + rx, 255);
                st[c][ry][rx] = __ldg(src + gy*WW + gx);
            }
        }
    }
    __syncthreads();

    int lrow = tid >> 3;
    int lcol0 = (tid & 7) << 2;
    int h = h0t + lrow;
    if (h < ah0 || h > ah1) return;     // row outside crop window: never read
    int w = w0t + lcol0;
    float fy = (float)h;
    float* ob = g_xw + (size_t)b*3*HH*WW + h*WW + w;
    float4 acc[3];
    #pragma unroll
    for (int k = 0; k < 4; k++) {
        // clamp column into the active range: clamped lanes are outside the
        // crop window (never read by K2) but keep smem indices inside the hull
        int wk = min(max(w + k, aw0), aw1);
        float fx = (float)wk;
        float sx = m[0]*fx + m[1]*fy + m[2];
        float sy = m[3]*fx + m[4]*fy + m[5];
        float cxs = fminf(fmaxf(sx, 0.f), 255.f);
        float cys = fminf(fmaxf(sy, 0.f), 255.f);
        float cx0f = floorf(cxs), cy0f = floorf(cys);
        int cx0 = (int)cx0f, cy0 = (int)cy0f;
        float cwx = cxs - cx0f, cwy = cys - cy0f;
        float w00 = (1.f-cwy)*(1.f-cwx), w01 = (1.f-cwy)*cwx;
        float w10 = cwy*(1.f-cwx),       w11 = cwy*cwx;
        int ix = cx0 - x_lo, iy = cy0 - y_lo;
        #pragma unroll
        for (int c = 0; c < 3; c++) {
            float v = st[c][iy][ix]*w00    + st[c][iy][ix+1]*w01
                    + st[c][iy+1][ix]*w10  + st[c][iy+1][ix+1]*w11;
            ((float*)&acc[c])[k] = v;
        }
    }
    #pragma unroll
    for (int c = 0; c < 3; c++)
        *(float4*)(ob + c*HH*WW) = acc[c];
}

// ============================================================================
// K2: crop resample (4 px/thread, scattered — proven) + brightness-gray partials
// ============================================================================
__global__ void __launch_bounds__(256) crop_kernel(CropP P) {
    int b = blockIdx.y;
    int pix0 = (blockIdx.x * 256 + threadIdx.x) * 4;
    float fx0 = P.cx0[b], fy0 = P.cy0[b], sf = P.sf[b];
    const float* xwb = g_xw + (size_t)b*3*HH*WW;
    float fb = P.fb[b];
    float gray = 0.f;
    float4 acc[3];
    #pragma unroll
    for (int k = 0; k < 4; k++) {
        int pix = pix0 + k;
        int vrow = pix / IMGS, ucol = pix % IMGS;
        float xs = fx0 + sf * (float)ucol;
        float ys = fy0 + sf * (float)vrow;
        xs = fminf(fmaxf(xs, 0.f), 255.f);
        ys = fminf(fmaxf(ys, 0.f), 255.f);
        float x0f = floorf(xs), y0f = floorf(ys);
        int xi = (int)x0f, yi = (int)y0f;
        float wx = xs - x0f, wy = ys - y0f;
        int x1 = min(xi + 1, 255), y1 = min(yi + 1, 255);
        float w00 = (1.f-wy)*(1.f-wx), w01 = (1.f-wy)*wx;
        float w10 = wy*(1.f-wx),       w11 = wy*wx;
        #pragma unroll
        for (int c = 0; c < 3; c++) {
            const float* img = xwb + c*HH*WW;
            float v = __ldg(img + yi*WW + xi)*w00 + __ldg(img + yi*WW + x1)*w01
                    + __ldg(img + y1*WW + xi)*w10 + __ldg(img + y1*WW + x1)*w11;
            ((float*)&acc[c])[k] = v;
            float yv = fminf(fmaxf(v * fb, 0.f), 1.f);
            gray += (c == 0 ? 0.299f : (c == 1 ? 0.587f : 0.114f)) * yv;
        }
    }
    float* ob = g_xc + (size_t)b*3*NPIX + pix0;
    #pragma unroll
    for (int c = 0; c < 3; c++)
        *(float4*)(ob + c*NPIX) = acc[c];

    __shared__ float sred[256];
    sred[threadIdx.x] = gray;
    __syncthreads();
    for (int stride = 128; stride > 0; stride >>= 1) {
        if (threadIdx.x < stride) sred[threadIdx.x] += sred[threadIdx.x + stride];
        __syncthreads();
    }
    if (threadIdx.x == 0) g_partial[b*NBLK + blockIdx.x] = sred[0];
}

// ============================================================================
// K3: fused mean-reduce + color jitter + SEPARABLE 3x9 blur + clip
// ============================================================================
__device__ __forceinline__ void jitter_px(float r0, float g0, float b0,
                                          float fb, float fc, float fs, float fh,
                                          float mean, int ap,
                                          float& ro, float& go, float& bo) {
    if (!ap) { ro = r0; go = g0; bo = b0; return; }
    float r = fminf(fmaxf(r0*fb, 0.f), 1.f);
    float g = fminf(fmaxf(g0*fb, 0.f), 1.f);
    float bl = fminf(fmaxf(b0*fb, 0.f), 1.f);
    r  = fminf(fmaxf(fc*r  + (1.f-fc)*mean, 0.f), 1.f);
    g  = fminf(fmaxf(fc*g  + (1.f-fc)*mean, 0.f), 1.f);
    bl = fminf(fmaxf(fc*bl + (1.f-fc)*mean, 0.f), 1.f);
    float gray = 0.299f*r + 0.587f*g + 0.114f*bl;
    r  = fminf(fmaxf(fs*r  + (1.f-fs)*gray, 0.f), 1.f);
    g  = fminf(fmaxf(fs*g  + (1.f-fs)*gray, 0.f), 1.f);
    bl = fminf(fmaxf(fs*bl + (1.f-fs)*gray, 0.f), 1.f);
    float maxc = fmaxf(r, fmaxf(g, bl));
    float minc = fminf(r, fminf(g, bl));
    float d = maxc - minc;
    const float eps = 1e-8f;
    float s_ = d / fmaxf(maxc, eps);
    float dd = fmaxf(d, eps);
    float h;
    if (maxc == r) {
        float t = (g - bl) / dd;
        h = t - floorf(t / 6.f) * 6.f;
    } else if (maxc == g) {
        h = (bl - r) / dd + 2.f;
    } else {
        h = (r - g) / dd + 4.f;
    }
    h = h / 6.f;
    if (d <= eps) h = 0.f;
    h += fh;
    float hm = h - floorf(h);
    float h6 = hm * 6.f;
    float fi = floorf(h6);
    float f = h6 - fi;
    float v = maxc;
    float pq = v * (1.f - s_);
    float q = v * (1.f - s_*f);
    float t2 = v * (1.f - s_*(1.f - f));
    int i = ((int)fi) % 6;
    float rr, gg, bb;
    switch (i) {
        case 0:  rr = v;  gg = t2; bb = pq; break;
        case 1:  rr = q;  gg = v;  bb = pq; break;
        case 2:  rr = pq; gg = v;  bb = t2; break;
        case 3:  rr = pq; gg = q;  bb = v;  break;
        case 4:  rr = t2; gg = pq; bb = v;  break;
        default: rr = v;  gg = pq; bb = q;  break;
    }
    ro = fminf(fmaxf(rr, 0.f), 1.f);
    go = fminf(fmaxf(gg, 0.f), 1.f);
    bo = fminf(fmaxf(bb, 0.f), 1.f);
}

#define TILE_H 14
#define HALO_H (TILE_H + 2)  /* 16 */
#define HALO_W (IMGS + 8)    /* 232 */

__global__ void __launch_bounds__(256) jb_kernel(JitP jp, BlurP bp, float* __restrict__ out) {
    int b = blockIdx.y;
    int ty0 = blockIdx.x * TILE_H;
    int tid = threadIdx.x;
    __shared__ float tile[3][HALO_H][HALO_W];
    __shared__ float red[256];

    red[tid] = (tid < NBLK) ? g_partial[b*NBLK + tid] : 0.f;
    __syncthreads();
    for (int stride = 128; stride > 0; stride >>= 1) {
        if (tid < stride) red[tid] += red[tid + stride];
        __syncthreads();
    }
    float mean = red[0] / (float)NPIX;
    __syncthreads();

    float fb = jp.fb[b], fc = jp.fc[b], fs = jp.fs[b], fh = jp.fhue[b];
    int apj = jp.ap[b];
    const float* xb = g_xc + (size_t)b*3*NPIX;

    for (int k = tid; k < HALO_H*HALO_W; k += 256) {
        int hr = k / HALO_W, hc = k % HALO_W;
        int gy = ty0 + hr - 1;
        gy = (gy < 0) ? -gy : ((gy > IMGS-1) ? 2*(IMGS-1) - gy : gy);
        int gx = hc - 4;
        gx = (gx < 0) ? -gx : ((gx > IMGS-1) ? 2*(IMGS-1) - gx : gx);
        int pix = gy*IMGS + gx;
        float r0 = __ldg(xb + pix);
        float g0 = __ldg(xb + NPIX + pix);
        float b0 = __ldg(xb + 2*NPIX + pix);
        float ro, go, bo;
        jitter_px(r0, g0, b0, fb, fc, fs, fh, mean, apj, ro, go, bo);
        tile[0][hr][hc] = ro;
        tile[1][hr][hc] = go;
        tile[2][hr][hc] = bo;
    }
    __syncthreads();

    int apb = bp.ap[b];

    if (apb) {
        // separable blur: thread = output column, rolling horizontal sums
        if (tid < IMGS) {
            int c = tid;
            float kyv0 = bp.ky[b][0], kyv1 = bp.ky[b][1], kyv2 = bp.ky[b][2];
            float kxv[9];
            #pragma unroll
            for (int i = 0; i < 9; i++) kxv[i] = bp.kx[b][i];

            float h0[3], h1[3];
            #pragma unroll
            for (int ch = 0; ch < 3; ch++) {
                float ra = 0.f;
                #pragma unroll
                for (int dx = 0; dx < 9; dx++) ra += kxv[dx] * tile[ch][0][c+dx];
                h0[ch] = ra;
                ra = 0.f;
                #pragma unroll
                for (int dx = 0; dx < 9; dx++) ra += kxv[dx] * tile[ch][1][c+dx];
                h1[ch] = ra;
            }
            float* ob = out + (size_t)b*3*NPIX + ty0*IMGS + c;
            for (int r = 0; r < TILE_H; r++) {
                #pragma unroll
                for (int ch = 0; ch < 3; ch++) {
                    float ra = 0.f;
                    #pragma unroll
                    for (int dx = 0; dx < 9; dx++) ra += kxv[dx] * tile[ch][r+2][c+dx];
                    float acc = kyv0 * h0[ch];
                    acc += kyv1 * h1[ch];
                    acc += kyv2 * ra;
                    h0[ch] = h1[ch];
                    h1[ch] = ra;
                    float o = fminf(fmaxf(acc, 0.f), 1.f);
                    ob[ch*NPIX + r*IMGS] = o;
                }
            }
        }
    } else {
        for (int t = tid; t < TILE_H*IMGS; t += 256) {
            int r = t / IMGS, c = t % IMGS;
            #pragma unroll
            for (int ch = 0; ch < 3; ch++) {
                float o = fminf(fmaxf(tile[ch][r+1][c+4], 0.f), 1.f);
                out[(size_t)b*3*NPIX + ch*NPIX + (ty0+r)*IMGS + c] = o;
            }
        }
    }
}

// ============================================================================
// Host: JAX threefry2x32 (partitionable mode) + host-side max-square DP
// ============================================================================
static inline uint32_t rotl32(uint32_t v, int s) { return (v << s) | (v >> (32 - s)); }

static void tf2x32(uint32_t k0, uint32_t k1, uint32_t x0, uint32_t x1,
                   uint32_t* o0, uint32_t* o1) {
    uint32_t ks2 = k0 ^ k1 ^ 0x1BD11BDAu;
    x0 += k0; x1 += k1;
    static const int R[2][4] = {{13,15,26,6},{17,29,16,24}};
    const uint32_t inj0[5] = {k1, ks2, k0, k1, ks2};
    const uint32_t inj1[5] = {ks2, k0, k1, ks2, k0};
    for (int g = 0; g < 5; g++) {
        for (int r = 0; r < 4; r++) {
            x0 += x1; x1 = rotl32(x1, R[g & 1][r]); x1 ^= x0;
        }
        x0 += inj0[g];
        x1 += inj1[g] + (uint32_t)(g + 1);
    }
    *o0 = x0; *o1 = x1;
}

static float h_u01(uint32_t k0, uint32_t k1, uint32_t i) {
    uint32_t a, b;
    tf2x32(k0, k1, 0u, i, &a, &b);
    uint32_t bits = a ^ b;
    uint32_t fbits = (bits >> 9) | 0x3f800000u;
    float f;
    memcpy(&f, &fbits, 4);
    return f - 1.0f;
}
static float h_uni(uint32_t k0, uint32_t k1, uint32_t i, float mn, float mx) {
    float u = h_u01(k0, k1, i);
    float v = u * (mx - mn) + mn;
    return (v < mn) ? mn : v;
}
static void h_split(uint32_t k0, uint32_t k1, int n, uint32_t out[][2]) {
    for (int i = 0; i < n; i++)
        tf2x32(k0, k1, 0u, (uint32_t)i, &out[i][0], &out[i][1]);
}

// host coverage: same logic as the device version; double precision dominates
// the ~1e-7 float noise while the >0.5 decision margin is ~1e-2.
static int h_cov(const float* m, double fx, double fy) {
    double sx = (double)m[0]*fx + (double)m[1]*fy + (double)m[2];
    double sy = (double)m[3]*fx + (double)m[4]*fy + (double)m[5];
    double x0f = floor(sx), y0f = floor(sy);
    int xi = (int)x0f, yi = (int)y0f;
    double wx = sx - x0f, wy = sy - y0f;
    double i00 = (yi   >= 0 && yi   < HH && xi   >= 0 && xi   < WW) ? 1.0 : 0.0;
    double i01 = (yi   >= 0 && yi   < HH && xi+1 >= 0 && xi+1 < WW) ? 1.0 : 0.0;
    double i10 = (yi+1 >= 0 && yi+1 < HH && xi   >= 0 && xi   < WW) ? 1.0 : 0.0;
    double i11 = (yi+1 >= 0 && yi+1 < HH && xi+1 >= 0 && xi+1 < WW) ? 1.0 : 0.0;
    double cov = i00*(1.0-wy)*(1.0-wx) + i01*(1.0-wy)*wx + i10*wy*(1.0-wx) + i11*wy*wx;
    return cov > 0.5 ? 1 : 0;
}

extern "C" void kernel_launch(void* const* d_in, const int* in_sizes, int n_in,
                              void* d_out, int out_size) {
    const float* x = (const float*)d_in[0];
    float* out = (float*)d_out;
    const float PI_F = 3.14159265358979323846f;

    uint32_t K3_[3][2];
    h_split(0u, 42u, 3, K3_);

    // ---- affine params ----
    uint32_t ka[6][2];
    h_split(K3_[0][0], K3_[0][1], 6, ka);
    static WarpP wp;
    for (int b = 0; b < BB; b++) {
        bool fhl = h_u01(ka[0][0], ka[0][1], b) < 0.5f;
        bool fvl = h_u01(ka[1][0], ka[1][1], b) < 0.5f;
        float ang = h_uni(ka[2][0], ka[2][1], b, -20.f, 20.f) * (PI_F / 180.f);
        float sc  = h_uni(ka[3][0], ka[3][1], b, 0.85f, 1.15f);
        float tx  = h_uni(ka[4][0], ka[4][1], b, -0.1f, 0.1f) * 256.f;
        float ty  = h_uni(ka[5][0], ka[5][1], b, -0.1f, 0.1f) * 256.f;
        float ca = cosf(ang) * sc, sa = sinf(ang) * sc;
        float a = ca, b2 = -sa, c2 = sa, d = ca;
        float cx = 127.5f, cy = 127.5f;
        float m02 = tx + cx - a*cx - b2*cy;
        float m12 = ty + cy - c2*cx - d*cy;
        float fxs = fhl ? -1.f : 1.f, fys = fvl ? -1.f : 1.f;
        float F02 = fhl ? 255.f : 0.f, F12 = fvl ? 255.f : 0.f;
        float M00 = a*fxs,  M01 = b2*fys, M02 = a*F02 + b2*F12 + m02;
        float M10 = c2*fxs, M11 = d*fys,  M12 = c2*F02 + d*F12 + m12;
        double det = (double)M00*(double)M11 - (double)M01*(double)M10;
        wp.inv[b][0] = (float)( (double)M11 / det);
        wp.inv[b][1] = (float)(-(double)M01 / det);
        wp.inv[b][2] = (float)(((double)M01*(double)M12 - (double)M02*(double)M11) / det);
        wp.inv[b][3] = (float)(-(double)M10 / det);
        wp.inv[b][4] = (float)( (double)M00 / det);
        wp.inv[b][5] = (float)(((double)M02*(double)M10 - (double)M00*(double)M12) / det);
    }

    // ---- host max-square DP (interval-based) ----
    static CropP cp;
    for (int b = 0; b < BB; b++) {
        const float* m = wp.inv[b];
        int L[HH], R[HH];
        for (int t = 0; t < HH; t++) {
            int Lv = 256, Rv = -1;
            for (int j = 0; j < WW; j++) {
                if (h_cov(m, (double)j, (double)t)) { if (j < Lv) Lv = j; Rv = j; }
            }
            L[t] = Lv; R[t] = Rv;
        }
        int bestS = 0, bestI = 0;
        for (int t = 0; t < HH; t++) {
            int bs = 0;
            if (R[t] >= L[t]) {
                int Lmax = L[t], Rmin = R[t];
                int s = 1;
                while (t - s >= 0) {
                    if (L[t-s] > Lmax) Lmax = L[t-s];
                    if (R[t-s] < Rmin) Rmin = R[t-s];
                    if (Rmin - Lmax + 1 >= s + 1) s++;
                    else break;
                }
                bs = s;
            }
            if (bs > bestS) { bestS = bs; bestI = t; }
        }
        int s = bestS, ii = bestI, x0, y0;
        if (s == 0) { x0 = WW/2; y0 = HH/2; s = 1; }
        else {
            int Lmax = -1;
            for (int r = ii - s + 1; r <= ii; r++) if (L[r] > Lmax) Lmax = L[r];
            int jj = Lmax + s - 1;
            x0 = jj + 1 - s; y0 = ii + 1 - s;
        }
        cp.cx0[b] = (float)x0;
        cp.cy0[b] = (float)y0;
        cp.sf[b]  = (float)s / (float)(IMGS - 1);

        int xlo = x0, xhi = x0 + s + 1; if (xhi > 255) xhi = 255;
        int ylo = y0, yhi = y0 + s + 1; if (yhi > 255) yhi = 255;
        wp.win[b][0] = xlo; wp.win[b][1] = xhi;
        wp.win[b][2] = ylo; wp.win[b][3] = yhi;
        unsigned long long mask = 0ull;
        for (int ty = ylo >> 5; ty <= (yhi >> 5); ty++)
            for (int tx = xlo >> 5; tx <= (xhi >> 5); tx++)
                mask |= 1ull << (ty*8 + tx);
        wp.tmask[b] = mask;
    }

    // ---- color jitter params ----
    uint32_t kc5[5][2];
    h_split(K3_[1][0], K3_[1][1], 5, kc5);
    static JitP jp;
    for (int b = 0; b < BB; b++) {
        float fb = h_uni(kc5[0][0], kc5[0][1], b, 0.7f, 1.3f);
        cp.fb[b] = fb; jp.fb[b] = fb;
        jp.fc[b]   = h_uni(kc5[1][0], kc5[1][1], b, 0.7f, 1.3f);
        jp.fs[b]   = h_uni(kc5[2][0], kc5[2][1], b, 0.7f, 1.3f);
        jp.fhue[b] = h_uni(kc5[3][0], kc5[3][1], b, -0.15f, 0.15f);
        jp.ap[b]   = (h_u01(kc5[4][0], kc5[4][1], b) < 0.7f) ? 1 : 0;
    }

    // ---- blur params ----
    uint32_t kb2[2][2];
    h_split(K3_[2][0], K3_[2][1], 2, kb2);
    static BlurP bp;
    for (int b = 0; b < BB; b++) {
        float sig = h_uni(kb2[0][0], kb2[0][1], b, 0.1f, 2.0f);
        float s2 = 2.f * sig * sig;
        float wy[3], wxv[9];
        float sumy = 0.f, sumx = 0.f;
        for (int i = 0; i < 3; i++) {
            float xk = (float)i - 1.f;
            wy[i] = expf(-(xk*xk) / s2);
            sumy += wy[i];
        }
        for (int i = 0; i < 9; i++) {
            float xk = (float)i - 4.f;
            wxv[i] = expf(-(xk*xk) / s2);
            sumx += wxv[i];
        }
        for (int i = 0; i < 3; i++) bp.ky[b][i] = wy[i] / sumy;
        for (int i = 0; i < 9; i++) bp.kx[b][i] = wxv[i] / sumx;
        bp.ap[b] = (h_u01(kb2[1][0], kb2[1][1], b) < 0.5f) ? 1 : 0;
    }

    // ---- launches ----
    warp_kernel<<<TILEBLKS, 256>>>(x, wp);
    dim3 g3(NBLK, BB);
    crop_kernel<<<g3, 256>>>(cp);
    dim3 g4(IMGS / TILE_H, BB);
    jb_kernel<<<g4, 256>>>(jp, bp, out);
}

// round 17
// speedup vs baseline: 1.1432x; 1.0226x over previous
#include <cuda_runtime.h>
#include <cstdint>
#include <cstring>
#include <cmath>

#define BB 64
#define HH 256
#define WW 256
#define IMGS 224
#define NPIX (IMGS*IMGS)   /* 50176 */
#define NBLK 49            /* 50176 / (256*4) */
#define TILEBLKS 4096      /* 64 images * 64 tiles (8x8 tiles of 32x32) */

#define RROWS 51           /* staged source rows (max) */
#define RCOLS 56           /* staged source cols (x_lo aligned to 4) */
#define RPITCH 60          /* smem pitch in floats (16B-aligned rows) */
#define NV4 14             /* float4 per staged row (max) */

// ---------------- device scratch (static globals; no allocs) ----------------
__device__ float g_xw[BB*3*HH*WW];     // warped 256x256 (planar)
__device__ float g_xc[BB*3*NPIX];      // cropped 224x224 (planar)
__device__ float g_partial[BB*NBLK];   // gray partial sums

// ---------------- parameter structs (passed by value) ----------------
struct WarpP { float inv[BB][6]; unsigned long long tmask[BB]; int win[BB][4]; };
struct CropP { float cx0[BB], cy0[BB], sf[BB], fb[BB]; };
struct JitP  { float fb[BB], fc[BB], fs[BB], fhue[BB]; int ap[BB]; };
struct BlurP { float ky[BB][3]; float kx[BB][9]; int ap[BB]; };

// ============================================================================
// K1: affine warp, smem-tiled 32x32 tiles, pixel-granular crop-window clipping
// ============================================================================
__global__ void __launch_bounds__(256) warp_kernel(const float* __restrict__ x, WarpP P) {
    __shared__ __align__(16) float st[3][RROWS][RPITCH];   // 36.7KB

    int tb = blockIdx.x;
    int b = tb >> 6;
    int tile = tb & 63;
    if (!((P.tmask[b] >> tile) & 1ull)) return;

    int w0t = (tile & 7) << 5;
    int h0t = (tile >> 3) << 5;
    const float* m = P.inv[b];
    int tid = threadIdx.x;

    // active sub-rectangle = tile ∩ crop window (non-empty: tmask passed)
    int aw0 = max(w0t, P.win[b][0]), aw1 = min(w0t + 31, P.win[b][1]);
    int ah0 = max(h0t, P.win[b][2]), ah1 = min(h0t + 31, P.win[b][3]);

    // source-coordinate hull over the active subrect corners (affine)
    float f_w0 = (float)aw0, f_w1 = (float)aw1;
    float f_h0 = (float)ah0, f_h1 = (float)ah1;
    float sx00 = m[0]*f_w0 + m[1]*f_h0 + m[2];
    float sx10 = m[0]*f_w1 + m[1]*f_h0 + m[2];
    float sx01 = m[0]*f_w0 + m[1]*f_h1 + m[2];
    float sx11 = m[0]*f_w1 + m[1]*f_h1 + m[2];
    float sy00 = m[3]*f_w0 + m[4]*f_h0 + m[5];
    float sy10 = m[3]*f_w1 + m[4]*f_h0 + m[5];
    float sy01 = m[3]*f_w0 + m[4]*f_h1 + m[5];
    float sy11 = m[3]*f_w1 + m[4]*f_h1 + m[5];
    float cminx = fminf(fminf(sx00, sx10), fminf(sx01, sx11));
    float cmaxx = fmaxf(fmaxf(sx00, sx10), fmaxf(sx01, sx11));
    float cminy = fminf(fminf(sy00, sy10), fminf(sy01, sy11));
    float cmaxy = fmaxf(fmaxf(sy00, sy10), fmaxf(sy01, sy11));
    cminx = fminf(fmaxf(cminx, 0.f), 255.f);
    cmaxx = fminf(fmaxf(cmaxx, 0.f), 255.f);
    cminy = fminf(fmaxf(cminy, 0.f), 255.f);
    cmaxy = fminf(fmaxf(cmaxy, 0.f), 255.f);
    int x_lo = (max((int)floorf(cminx) - 1, 0)) & ~3;     // 4-aligned
    int y_lo = max((int)floorf(cminy) - 1, 0);
    int rows_needed = min(RROWS, (int)floorf(cmaxy) + 3 - y_lo);
    int nv4_needed  = min(NV4, (((int)floorf(cmaxx) + 3 - x_lo) + 3) >> 2);
    if (rows_needed < 1) rows_needed = 1;
    if (nv4_needed < 1) nv4_needed = 1;

    const float* xb = x + (size_t)b*3*HH*WW;
    if (x_lo + (RCOLS - 1) <= 255) {
        // interior fast path: float4 staging (no column clamp needed)
        #pragma unroll
        for (int c = 0; c < 3; c++) {
            const float4* src = (const float4*)(xb + c*HH*WW + x_lo);
            float4* dst = (float4*)&st[c][0][0];
            for (int k = tid; k < rows_needed*nv4_needed; k += 256) {
                int ry = k / nv4_needed;
                int rx4 = k - ry*nv4_needed;
                int gy = min(y_lo + ry, 255);
                dst[ry*(RPITCH/4) + rx4] = __ldg(src + gy*(WW/4) + rx4);
            }
        }
    } else {
        // edge path: scalar staging with per-element clamp (duplicates edge col)
        int cols_needed = nv4_needed * 4;
        #pragma unroll
        for (int c = 0; c < 3; c++) {
            const float* src = xb + c*HH*WW;
            for (int k = tid; k < rows_needed*cols_needed; k += 256) {
                int ry = k / cols_needed;
                int rx = k - ry*cols_needed;
                int gy = min(y_lo + ry, 255);
                int gx = min(x_lo + rx, 255);
                st[c][ry][rx] = __ldg(src + gy*WW + gx);
            }
        }
    }
    __syncthreads();

    int lrow = tid >> 3;
    int lcol0 = (tid & 7) << 2;
    int h = h0t + lrow;
    if (h < ah0 || h > ah1) return;     // row outside crop window: never read
    int w = w0t + lcol0;
    float fy = (float)h;
    float* ob = g_xw + (size_t)b*3*HH*WW + h*WW + w;
    float4 acc[3];
    #pragma unroll
    for (int k = 0; k < 4; k++) {
        // clamp column into the active range: clamped lanes are outside the
        // crop window (never read by K2) but keep smem indices inside the hull
        int wk = min(max(w + k, aw0), aw1);
        float fx = (float)wk;
        float sx = m[0]*fx + m[1]*fy + m[2];
        float sy = m[3]*fx + m[4]*fy + m[5];
        float cxs = fminf(fmaxf(sx, 0.f), 255.f);
        float cys = fminf(fmaxf(sy, 0.f), 255.f);
        float cx0f = floorf(cxs), cy0f = floorf(cys);
        int cx0 = (int)cx0f, cy0 = (int)cy0f;
        float cwx = cxs - cx0f, cwy = cys - cy0f;
        float w00 = (1.f-cwy)*(1.f-cwx), w01 = (1.f-cwy)*cwx;
        float w10 = cwy*(1.f-cwx),       w11 = cwy*cwx;
        int ix = cx0 - x_lo, iy = cy0 - y_lo;
        #pragma unroll
        for (int c = 0; c < 3; c++) {
            float v = st[c][iy][ix]*w00    + st[c][iy][ix+1]*w01
                    + st[c][iy+1][ix]*w10  + st[c][iy+1][ix+1]*w11;
            ((float*)&acc[c])[k] = v;
        }
    }
    #pragma unroll
    for (int c = 0; c < 3; c++)
        *(float4*)(ob + c*HH*WW) = acc[c];
}

// ============================================================================
// K2: crop resample (4 px/thread, scattered — proven) + brightness-gray partials
// ============================================================================
__global__ void __launch_bounds__(256) crop_kernel(CropP P) {
    int b = blockIdx.y;
    int pix0 = (blockIdx.x * 256 + threadIdx.x) * 4;
    float fx0 = P.cx0[b], fy0 = P.cy0[b], sf = P.sf[b];
    const float* xwb = g_xw + (size_t)b*3*HH*WW;
    float fb = P.fb[b];
    float gray = 0.f;
    float4 acc[3];
    #pragma unroll
    for (int k = 0; k < 4; k++) {
        int pix = pix0 + k;
        int vrow = pix / IMGS, ucol = pix % IMGS;
        float xs = fx0 + sf * (float)ucol;
        float ys = fy0 + sf * (float)vrow;
        xs = fminf(fmaxf(xs, 0.f), 255.f);
        ys = fminf(fmaxf(ys, 0.f), 255.f);
        float x0f = floorf(xs), y0f = floorf(ys);
        int xi = (int)x0f, yi = (int)y0f;
        float wx = xs - x0f, wy = ys - y0f;
        int x1 = min(xi + 1, 255), y1 = min(yi + 1, 255);
        float w00 = (1.f-wy)*(1.f-wx), w01 = (1.f-wy)*wx;
        float w10 = wy*(1.f-wx),       w11 = wy*wx;
        #pragma unroll
        for (int c = 0; c < 3; c++) {
            const float* img = xwb + c*HH*WW;
            float v = __ldg(img + yi*WW + xi)*w00 + __ldg(img + yi*WW + x1)*w01
                    + __ldg(img + y1*WW + xi)*w10 + __ldg(img + y1*WW + x1)*w11;
            ((float*)&acc[c])[k] = v;
            float yv = fminf(fmaxf(v * fb, 0.f), 1.f);
            gray += (c == 0 ? 0.299f : (c == 1 ? 0.587f : 0.114f)) * yv;
        }
    }
    float* ob = g_xc + (size_t)b*3*NPIX + pix0;
    #pragma unroll
    for (int c = 0; c < 3; c++)
        *(float4*)(ob + c*NPIX) = acc[c];

    __shared__ float sred[256];
    sred[threadIdx.x] = gray;
    __syncthreads();
    for (int stride = 128; stride > 0; stride >>= 1) {
        if (threadIdx.x < stride) sred[threadIdx.x] += sred[threadIdx.x + stride];
        __syncthreads();
    }
    if (threadIdx.x == 0) g_partial[b*NBLK + blockIdx.x] = sred[0];
}

// ============================================================================
// K3: fused mean-reduce + color jitter + SEPARABLE 3x9 blur + clip
//     224 threads; apb==0 blocks take a pure elementwise path (no smem tile)
// ============================================================================
__device__ __forceinline__ void jitter_px(float r0, float g0, float b0,
                                          float fb, float fc, float fs, float fh,
                                          float mean, int ap,
                                          float& ro, float& go, float& bo) {
    if (!ap) { ro = r0; go = g0; bo = b0; return; }
    float r = fminf(fmaxf(r0*fb, 0.f), 1.f);
    float g = fminf(fmaxf(g0*fb, 0.f), 1.f);
    float bl = fminf(fmaxf(b0*fb, 0.f), 1.f);
    r  = fminf(fmaxf(fc*r  + (1.f-fc)*mean, 0.f), 1.f);
    g  = fminf(fmaxf(fc*g  + (1.f-fc)*mean, 0.f), 1.f);
    bl = fminf(fmaxf(fc*bl + (1.f-fc)*mean, 0.f), 1.f);
    float gray = 0.299f*r + 0.587f*g + 0.114f*bl;
    r  = fminf(fmaxf(fs*r  + (1.f-fs)*gray, 0.f), 1.f);
    g  = fminf(fmaxf(fs*g  + (1.f-fs)*gray, 0.f), 1.f);
    bl = fminf(fmaxf(fs*bl + (1.f-fs)*gray, 0.f), 1.f);
    float maxc = fmaxf(r, fmaxf(g, bl));
    float minc = fminf(r, fminf(g, bl));
    float d = maxc - minc;
    const float eps = 1e-8f;
    float s_ = d / fmaxf(maxc, eps);
    float dd = fmaxf(d, eps);
    float h;
    if (maxc == r) {
        float t = (g - bl) / dd;
        h = t - floorf(t / 6.f) * 6.f;
    } else if (maxc == g) {
        h = (bl - r) / dd + 2.f;
    } else {
        h = (r - g) / dd + 4.f;
    }
    h = h / 6.f;
    if (d <= eps) h = 0.f;
    h += fh;
    float hm = h - floorf(h);
    float h6 = hm * 6.f;
    float fi = floorf(h6);
    float f = h6 - fi;
    float v = maxc;
    float pq = v * (1.f - s_);
    float q = v * (1.f - s_*f);
    float t2 = v * (1.f - s_*(1.f - f));
    int i = ((int)fi) % 6;
    float rr, gg, bb;
    switch (i) {
        case 0:  rr = v;  gg = t2; bb = pq; break;
        case 1:  rr = q;  gg = v;  bb = pq; break;
        case 2:  rr = pq; gg = v;  bb = t2; break;
        case 3:  rr = pq; gg = q;  bb = v;  break;
        case 4:  rr = t2; gg = pq; bb = v;  break;
        default: rr = v;  gg = pq; bb = q;  break;
    }
    ro = fminf(fmaxf(rr, 0.f), 1.f);
    go = fminf(fmaxf(gg, 0.f), 1.f);
    bo = fminf(fmaxf(bb, 0.f), 1.f);
}

#define TILE_H 14
#define HALO_H (TILE_H + 2)  /* 16 */
#define HALO_W (IMGS + 8)    /* 232 */
#define JBT 224              /* K3 threads */

__global__ void __launch_bounds__(JBT) jb_kernel(JitP jp, BlurP bp, float* __restrict__ out) {
    int b = blockIdx.y;
    int ty0 = blockIdx.x * TILE_H;
    int tid = threadIdx.x;
    __shared__ float tile[3][HALO_H][HALO_W];
    __shared__ float red[256];

    red[tid] = (tid < NBLK) ? g_partial[b*NBLK + tid] : 0.f;
    if (tid < 256 - JBT) red[JBT + tid] = 0.f;
    __syncthreads();
    for (int stride = 128; stride > 0; stride >>= 1) {
        if (tid < stride) red[tid] += red[tid + stride];
        __syncthreads();
    }
    float mean = red[0] / (float)NPIX;

    float fb = jp.fb[b], fc = jp.fc[b], fs = jp.fs[b], fh = jp.fhue[b];
    int apj = jp.ap[b];
    int apb = bp.ap[b];
    const float* xb = g_xc + (size_t)b*3*NPIX;

    if (!apb) {
        // elementwise path: no blur -> no halo, no tile, no barriers needed
        int c = tid;
        const float* ib = xb + ty0*IMGS + c;
        float* ob = out + (size_t)b*3*NPIX + ty0*IMGS + c;
        #pragma unroll 2
        for (int r = 0; r < TILE_H; r++) {
            float r0 = __ldg(ib + r*IMGS);
            float g0 = __ldg(ib + NPIX + r*IMGS);
            float b0 = __ldg(ib + 2*NPIX + r*IMGS);
            float ro, go, bo;
            jitter_px(r0, g0, b0, fb, fc, fs, fh, mean, apj, ro, go, bo);
            ob[r*IMGS]          = fminf(fmaxf(ro, 0.f), 1.f);
            ob[NPIX + r*IMGS]   = fminf(fmaxf(go, 0.f), 1.f);
            ob[2*NPIX + r*IMGS] = fminf(fmaxf(bo, 0.f), 1.f);
        }
        return;
    }

    // blur path: halo + jitter into smem, then separable blur
    __syncthreads();
    for (int k = tid; k < HALO_H*HALO_W; k += JBT) {
        int hr = k / HALO_W, hc = k % HALO_W;
        int gy = ty0 + hr - 1;
        gy = (gy < 0) ? -gy : ((gy > IMGS-1) ? 2*(IMGS-1) - gy : gy);
        int gx = hc - 4;
        gx = (gx < 0) ? -gx : ((gx > IMGS-1) ? 2*(IMGS-1) - gx : gx);
        int pix = gy*IMGS + gx;
        float r0 = __ldg(xb + pix);
        float g0 = __ldg(xb + NPIX + pix);
        float b0 = __ldg(xb + 2*NPIX + pix);
        float ro, go, bo;
        jitter_px(r0, g0, b0, fb, fc, fs, fh, mean, apj, ro, go, bo);
        tile[0][hr][hc] = ro;
        tile[1][hr][hc] = go;
        tile[2][hr][hc] = bo;
    }
    __syncthreads();

    // separable blur: thread = output column, rolling horizontal sums
    {
        int c = tid;
        float kyv0 = bp.ky[b][0], kyv1 = bp.ky[b][1], kyv2 = bp.ky[b][2];
        float kxv[9];
        #pragma unroll
        for (int i = 0; i < 9; i++) kxv[i] = bp.kx[b][i];

        float h0[3], h1[3];
        #pragma unroll
        for (int ch = 0; ch < 3; ch++) {
            float ra = 0.f;
            #pragma unroll
            for (int dx = 0; dx < 9; dx++) ra += kxv[dx] * tile[ch][0][c+dx];
            h0[ch] = ra;
            ra = 0.f;
            #pragma unroll
            for (int dx = 0; dx < 9; dx++) ra += kxv[dx] * tile[ch][1][c+dx];
            h1[ch] = ra;
        }
        float* ob = out + (size_t)b*3*NPIX + ty0*IMGS + c;
        for (int r = 0; r < TILE_H; r++) {
            #pragma unroll
            for (int ch = 0; ch < 3; ch++) {
                float ra = 0.f;
                #pragma unroll
                for (int dx = 0; dx < 9; dx++) ra += kxv[dx] * tile[ch][r+2][c+dx];
                float acc = kyv0 * h0[ch];
                acc += kyv1 * h1[ch];
                acc += kyv2 * ra;
                h0[ch] = h1[ch];
                h1[ch] = ra;
                float o = fminf(fmaxf(acc, 0.f), 1.f);
                ob[ch*NPIX + r*IMGS] = o;
            }
        }
    }
}

// ============================================================================
// Host: JAX threefry2x32 (partitionable mode) + host-side max-square DP
// ============================================================================
static inline uint32_t rotl32(uint32_t v, int s) { return (v << s) | (v >> (32 - s)); }

static void tf2x32(uint32_t k0, uint32_t k1, uint32_t x0, uint32_t x1,
                   uint32_t* o0, uint32_t* o1) {
    uint32_t ks2 = k0 ^ k1 ^ 0x1BD11BDAu;
    x0 += k0; x1 += k1;
    static const int R[2][4] = {{13,15,26,6},{17,29,16,24}};
    const uint32_t inj0[5] = {k1, ks2, k0, k1, ks2};
    const uint32_t inj1[5] = {ks2, k0, k1, ks2, k0};
    for (int g = 0; g < 5; g++) {
        for (int r = 0; r < 4; r++) {
            x0 += x1; x1 = rotl32(x1, R[g & 1][r]); x1 ^= x0;
        }
        x0 += inj0[g];
        x1 += inj1[g] + (uint32_t)(g + 1);
    }
    *o0 = x0; *o1 = x1;
}

static float h_u01(uint32_t k0, uint32_t k1, uint32_t i) {
    uint32_t a, b;
    tf2x32(k0, k1, 0u, i, &a, &b);
    uint32_t bits = a ^ b;
    uint32_t fbits = (bits >> 9) | 0x3f800000u;
    float f;
    memcpy(&f, &fbits, 4);
    return f - 1.0f;
}
static float h_uni(uint32_t k0, uint32_t k1, uint32_t i, float mn, float mx) {
    float u = h_u01(k0, k1, i);
    float v = u * (mx - mn) + mn;
    return (v < mn) ? mn : v;
}
static void h_split(uint32_t k0, uint32_t k1, int n, uint32_t out[][2]) {
    for (int i = 0; i < n; i++)
        tf2x32(k0, k1, 0u, (uint32_t)i, &out[i][0], &out[i][1]);
}

// host coverage: same logic as the device version; double precision dominates
// the ~1e-7 float noise while the >0.5 decision margin is ~1e-2.
static int h_cov(const float* m, double fx, double fy) {
    double sx = (double)m[0]*fx + (double)m[1]*fy + (double)m[2];
    double sy = (double)m[3]*fx + (double)m[4]*fy + (double)m[5];
    double x0f = floor(sx), y0f = floor(sy);
    int xi = (int)x0f, yi = (int)y0f;
    double wx = sx - x0f, wy = sy - y0f;
    double i00 = (yi   >= 0 && yi   < HH && xi   >= 0 && xi   < WW) ? 1.0 : 0.0;
    double i01 = (yi   >= 0 && yi   < HH && xi+1 >= 0 && xi+1 < WW) ? 1.0 : 0.0;
    double i10 = (yi+1 >= 0 && yi+1 < HH && xi   >= 0 && xi   < WW) ? 1.0 : 0.0;
    double i11 = (yi+1 >= 0 && yi+1 < HH && xi+1 >= 0 && xi+1 < WW) ? 1.0 : 0.0;
    double cov = i00*(1.0-wy)*(1.0-wx) + i01*(1.0-wy)*wx + i10*wy*(1.0-wx) + i11*wy*wx;
    return cov > 0.5 ? 1 : 0;
}

extern "C" void kernel_launch(void* const* d_in, const int* in_sizes, int n_in,
                              void* d_out, int out_size) {
    const float* x = (const float*)d_in[0];
    float* out = (float*)d_out;
    const float PI_F = 3.14159265358979323846f;

    uint32_t K3_[3][2];
    h_split(0u, 42u, 3, K3_);

    // ---- affine params ----
    uint32_t ka[6][2];
    h_split(K3_[0][0], K3_[0][1], 6, ka);
    static WarpP wp;
    for (int b = 0; b < BB; b++) {
        bool fhl = h_u01(ka[0][0], ka[0][1], b) < 0.5f;
        bool fvl = h_u01(ka[1][0], ka[1][1], b) < 0.5f;
        float ang = h_uni(ka[2][0], ka[2][1], b, -20.f, 20.f) * (PI_F / 180.f);
        float sc  = h_uni(ka[3][0], ka[3][1], b, 0.85f, 1.15f);
        float tx  = h_uni(ka[4][0], ka[4][1], b, -0.1f, 0.1f) * 256.f;
        float ty  = h_uni(ka[5][0], ka[5][1], b, -0.1f, 0.1f) * 256.f;
        float ca = cosf(ang) * sc, sa = sinf(ang) * sc;
        float a = ca, b2 = -sa, c2 = sa, d = ca;
        float cx = 127.5f, cy = 127.5f;
        float m02 = tx + cx - a*cx - b2*cy;
        float m12 = ty + cy - c2*cx - d*cy;
        float fxs = fhl ? -1.f : 1.f, fys = fvl ? -1.f : 1.f;
        float F02 = fhl ? 255.f : 0.f, F12 = fvl ? 255.f : 0.f;
        float M00 = a*fxs,  M01 = b2*fys, M02 = a*F02 + b2*F12 + m02;
        float M10 = c2*fxs, M11 = d*fys,  M12 = c2*F02 + d*F12 + m12;
        double det = (double)M00*(double)M11 - (double)M01*(double)M10;
        wp.inv[b][0] = (float)( (double)M11 / det);
        wp.inv[b][1] = (float)(-(double)M01 / det);
        wp.inv[b][2] = (float)(((double)M01*(double)M12 - (double)M02*(double)M11) / det);
        wp.inv[b][3] = (float)(-(double)M10 / det);
        wp.inv[b][4] = (float)( (double)M00 / det);
        wp.inv[b][5] = (float)(((double)M02*(double)M10 - (double)M00*(double)M12) / det);
    }

    // ---- host max-square DP (interval-based) ----
    static CropP cp;
    for (int b = 0; b < BB; b++) {
        const float* m = wp.inv[b];
        int L[HH], R[HH];
        for (int t = 0; t < HH; t++) {
            int Lv = 256, Rv = -1;
            for (int j = 0; j < WW; j++) {
                if (h_cov(m, (double)j, (double)t)) { if (j < Lv) Lv = j; Rv = j; }
            }
            L[t] = Lv; R[t] = Rv;
        }
        int bestS = 0, bestI = 0;
        for (int t = 0; t < HH; t++) {
            int bs = 0;
            if (R[t] >= L[t]) {
                int Lmax = L[t], Rmin = R[t];
                int s = 1;
                while (t - s >= 0) {
                    if (L[t-s] > Lmax) Lmax = L[t-s];
                    if (R[t-s] < Rmin) Rmin = R[t-s];
                    if (Rmin - Lmax + 1 >= s + 1) s++;
                    else break;
                }
                bs = s;
            }
            if (bs > bestS) { bestS = bs; bestI = t; }
        }
        int s = bestS, ii = bestI, x0, y0;
        if (s == 0) { x0 = WW/2; y0 = HH/2; s = 1; }
        else {
            int Lmax = -1;
            for (int r = ii - s + 1; r <= ii; r++) if (L[r] > Lmax) Lmax = L[r];
            int jj = Lmax + s - 1;
            x0 = jj + 1 - s; y0 = ii + 1 - s;
        }
        cp.cx0[b] = (float)x0;
        cp.cy0[b] = (float)y0;
        cp.sf[b]  = (float)s / (float)(IMGS - 1);

        int xlo = x0, xhi = x0 + s + 1; if (xhi > 255) xhi = 255;
        int ylo = y0, yhi = y0 + s + 1; if (yhi > 255) yhi = 255;
        wp.win[b][0] = xlo; wp.win[b][1] = xhi;
        wp.win[b][2] = ylo; wp.win[b][3] = yhi;
        unsigned long long mask = 0ull;
        for (int ty = ylo >> 5; ty <= (yhi >> 5); ty++)
            for (int tx = xlo >> 5; tx <= (xhi >> 5); tx++)
                mask |= 1ull << (ty*8 + tx);
        wp.tmask[b] = mask;
    }

    // ---- color jitter params ----
    uint32_t kc5[5][2];
    h_split(K3_[1][0], K3_[1][1], 5, kc5);
    static JitP jp;
    for (int b = 0; b < BB; b++) {
        float fb = h_uni(kc5[0][0], kc5[0][1], b, 0.7f, 1.3f);
        cp.fb[b] = fb; jp.fb[b] = fb;
        jp.fc[b]   = h_uni(kc5[1][0], kc5[1][1], b, 0.7f, 1.3f);
        jp.fs[b]   = h_uni(kc5[2][0], kc5[2][1], b, 0.7f, 1.3f);
        jp.fhue[b] = h_uni(kc5[3][0], kc5[3][1], b, -0.15f, 0.15f);
        jp.ap[b]   = (h_u01(kc5[4][0], kc5[4][1], b) < 0.7f) ? 1 : 0;
    }

    // ---- blur params ----
    uint32_t kb2[2][2];
    h_split(K3_[2][0], K3_[2][1], 2, kb2);
    static BlurP bp;
    for (int b = 0; b < BB; b++) {
        float sig = h_uni(kb2[0][0], kb2[0][1], b, 0.1f, 2.0f);
        float s2 = 2.f * sig * sig;
        float wy[3], wxv[9];
        float sumy = 0.f, sumx = 0.f;
        for (int i = 0; i < 3; i++) {
            float xk = (float)i - 1.f;
            wy[i] = expf(-(xk*xk) / s2);
            sumy += wy[i];
        }
        for (int i = 0; i < 9; i++) {
            float xk = (float)i - 4.f;
            wxv[i] = expf(-(xk*xk) / s2);
            sumx += wxv[i];
        }
        for (int i = 0; i < 3; i++) bp.ky[b][i] = wy[i] / sumy;
        for (int i = 0; i < 9; i++) bp.kx[b][i] = wxv[i] / sumx;
        bp.ap[b] = (h_u01(kb2[1][0], kb2[1][1], b) < 0.5f) ? 1 : 0;
    }

    // ---- launches ----
    warp_kernel<<<TILEBLKS, 256>>>(x, wp);
    dim3 g3(NBLK, BB);
    crop_kernel<<<g3, 256>>>(cp);
    dim3 g4(IMGS / TILE_H, BB);
    jb_kernel<<<g4, JBT>>>(jp, bp, out);
}